// round 13
// baseline (speedup 1.0000x reference)
#include <cuda_runtime.h>
#include <cuda_bf16.h>
#include <cstdint>

// ---------------- problem constants ----------------
constexpr int Fdim = 2048;
constexpr int HID  = 1100;
constexpr int NCLS = 512;
constexpr int M1   = 8192;     // 64 * 512/4
constexpr int M2   = 2048;     // M1 / 4
constexpr int N1PAD = 1152;    // HID padded to mult of 128 (GEMM1 N)
constexpr int K2PAD = 1152;    // = N1PAD; GEMM2 K padding
constexpr int MH   = M1 / 2;   // 4096-row halves

// ---------------- scratch (no cudaMalloc allowed) ----------------
__device__ __align__(16) __nv_bfloat16 g_g1 [M1 * Fdim];     // conv1 out (bf16)  32 MB
__device__ __align__(16) __nv_bfloat16 g_g2 [M2 * K2PAD];    // fused conv2 out   4.7 MB
__device__ __align__(16) __nv_bfloat16 g_bt1[N1PAD * Fdim];  // prop1_W^T bf16    4.7 MB
__device__ __align__(16) __nv_bfloat16 g_bt2[NCLS * K2PAD];  // prop2_W^T bf16    1.2 MB

// ---------------- helpers ----------------
__device__ __forceinline__ uint32_t smem_u32(const void* p) {
    uint32_t a;
    asm("{ .reg .u64 t; cvta.to.shared.u64 t, %1; cvt.u32.u64 %0, t; }" : "=r"(a) : "l"(p));
    return a;
}

#define CP_ASYNC16(saddr, gptr) \
    asm volatile("cp.async.cg.shared.global [%0], [%1], 16;" :: "r"(saddr), "l"(gptr))
#define CP_COMMIT()  asm volatile("cp.async.commit_group;" ::: "memory")
#define CP_WAIT1()   asm volatile("cp.async.wait_group 1;" ::: "memory")
#define CP_WAIT0()   asm volatile("cp.async.wait_group 0;" ::: "memory")

#define LDSM_X4(r, addr) \
    asm volatile("ldmatrix.sync.aligned.m8n8.x4.shared.b16 {%0,%1,%2,%3}, [%4];" \
        : "=r"((r)[0]), "=r"((r)[1]), "=r"((r)[2]), "=r"((r)[3]) : "r"(addr))

#define MMA_BF16(c, a, b0, b1) \
    asm volatile("mma.sync.aligned.m16n8k16.row.col.f32.bf16.bf16.f32 " \
        "{%0,%1,%2,%3}, {%4,%5,%6,%7}, {%8,%9}, {%0,%1,%2,%3};" \
        : "+f"((c)[0]), "+f"((c)[1]), "+f"((c)[2]), "+f"((c)[3]) \
        : "r"((a)[0]), "r"((a)[1]), "r"((a)[2]), "r"((a)[3]), "r"(b0), "r"(b1))

__device__ __forceinline__ float lrelu(float v) { return (v >= 0.f) ? v : 0.01f * v; }

// ---------------- node conv (FD compile-time): out[r,:] = bf16(sum_p x[4r+p,:]*w[p,:]) ----------------
template<int FD>
__global__ void node_conv4_bf16(const float* __restrict__ x, const float* __restrict__ w,
                                __nv_bfloat16* __restrict__ out, int rows) {
    constexpr int F4 = FD / 4, F8 = FD / 8;
    long idx = (long)blockIdx.x * blockDim.x + threadIdx.x;
    if (idx >= (long)rows * F8) return;
    int r = (int)(idx / F8);
    int j = (int)(idx % F8);
    const float4* x4 = (const float4*)x;
    const float4* w4 = (const float4*)w;
    float4 a0 = make_float4(0.f, 0.f, 0.f, 0.f);
    float4 a1 = make_float4(0.f, 0.f, 0.f, 0.f);
#pragma unroll
    for (int p = 0; p < 4; ++p) {
        const float4* xr = x4 + (long)(4 * r + p) * F4 + 2 * j;
        const float4* wr = w4 + p * F4 + 2 * j;
        float4 xv0 = xr[0], wv0 = wr[0];
        float4 xv1 = xr[1], wv1 = wr[1];
        a0.x = fmaf(xv0.x, wv0.x, a0.x); a0.y = fmaf(xv0.y, wv0.y, a0.y);
        a0.z = fmaf(xv0.z, wv0.z, a0.z); a0.w = fmaf(xv0.w, wv0.w, a0.w);
        a1.x = fmaf(xv1.x, wv1.x, a1.x); a1.y = fmaf(xv1.y, wv1.y, a1.y);
        a1.z = fmaf(xv1.z, wv1.z, a1.z); a1.w = fmaf(xv1.w, wv1.w, a1.w);
    }
    __nv_bfloat162 b0 = __floats2bfloat162_rn(a0.x, a0.y);
    __nv_bfloat162 b1 = __floats2bfloat162_rn(a0.z, a0.w);
    __nv_bfloat162 b2 = __floats2bfloat162_rn(a1.x, a1.y);
    __nv_bfloat162 b3 = __floats2bfloat162_rn(a1.z, a1.w);
    uint4 v;
    v.x = *(uint32_t*)&b0; v.y = *(uint32_t*)&b1;
    v.z = *(uint32_t*)&b2; v.w = *(uint32_t*)&b3;
    ((uint4*)out)[idx] = v;
}

// ---------------- transpose + bf16 round + zero pad:  W[K][N] -> Bt[Npad][Kpad] ----------------
__global__ void transpose_bf16(const float* __restrict__ W, __nv_bfloat16* __restrict__ Bt,
                               int K, int N, int Kpad, int Npad) {
    __shared__ float t[32][33];
    int k0 = blockIdx.x * 32, n0 = blockIdx.y * 32;
#pragma unroll
    for (int i = 0; i < 4; ++i) {
        int k = k0 + threadIdx.y + i * 8;
        int n = n0 + threadIdx.x;
        t[threadIdx.y + i * 8][threadIdx.x] = (k < K && n < N) ? W[(long)k * N + n] : 0.f;
    }
    __syncthreads();
#pragma unroll
    for (int i = 0; i < 4; ++i) {
        int n = n0 + threadIdx.y + i * 8;
        int k = k0 + threadIdx.x;
        if (n < Npad && k < Kpad)
            Bt[(long)n * Kpad + k] = __float2bfloat16_rn(t[threadIdx.x][threadIdx.y + i * 8]);
    }
}

// ================= GEMM1 (fused conv2): CTA 128x128, 256 thr, warp 64x32, 3-stage (proven) =================
constexpr int ST1   = 32768;               // A 16KB + B 16KB
constexpr int SMEM1 = 3 * ST1;             // 98304 B

__global__ __launch_bounds__(256, 2)
void gemm1_fused(const __nv_bfloat16* __restrict__ A, const __nv_bfloat16* __restrict__ Bt,
                 const float* __restrict__ bias, const float* __restrict__ w2,
                 __nv_bfloat16* __restrict__ g2out,
                 int Ncols, int lda, int ldb, int ntiles, int g2stride) {
    extern __shared__ char smem[];
    const uint32_t sb = smem_u32(smem);
    const int tid  = threadIdx.x;
    const int lane = tid & 31, warp = tid >> 5;
    const int wm = warp & 1, wn = warp >> 1;
    const int row0 = blockIdx.y * 128;
    const int col0 = blockIdx.x * 128;

    const char* ag[4]; uint32_t asw[4];
    const char* bg[4]; uint32_t bsw[4];
#pragma unroll
    for (int i = 0; i < 4; ++i) {
        int idx = i * 256 + tid;
        int row = idx >> 3, col = idx & 7;
        ag[i]  = (const char*)(A + (size_t)(row0 + row) * lda) + col * 16;
        asw[i] = sb + (uint32_t)(row * 128 + ((col ^ (row & 7)) << 4));
        bg[i]  = (const char*)(Bt + (size_t)(col0 + row) * ldb) + col * 16;
        bsw[i] = sb + 16384u + (uint32_t)(row * 128 + ((col ^ (row & 7)) << 4));
    }

    uint32_t a_rb[4]; int a_r7[4];
    {
        int rc = wm * 64 + (lane & 15);
#pragma unroll
        for (int i = 0; i < 4; ++i) { int r = rc + i * 16; a_rb[i] = (uint32_t)r << 7; a_r7[i] = r & 7; }
    }
    const int a_hi = lane >> 4;
    uint32_t b_rb[2]; int b_r7[2];
    {
        int rc = wn * 32 + ((lane >> 4) << 3) + (lane & 7);
#pragma unroll
        for (int g = 0; g < 2; ++g) { int r = rc + g * 16; b_rb[g] = (uint32_t)r << 7; b_r7[g] = r & 7; }
    }
    const int b_hi = (lane >> 3) & 1;

    float acc[4][4][4] = {};

#pragma unroll
    for (int s = 0; s < 2; ++s) {
        const uint32_t so = (uint32_t)s * ST1;
        const int koff = s * 128;
#pragma unroll
        for (int i = 0; i < 4; ++i) CP_ASYNC16(asw[i] + so, ag[i] + koff);
#pragma unroll
        for (int i = 0; i < 4; ++i) CP_ASYNC16(bsw[i] + so, bg[i] + koff);
        CP_COMMIT();
    }

    int cur = 0, nxt = 2;
    for (int kt = 0; kt < ntiles; ++kt) {
        if (kt + 1 < ntiles) { CP_WAIT1(); } else { CP_WAIT0(); }
        __syncthreads();

        if (kt + 2 < ntiles) {
            const uint32_t so = (uint32_t)nxt * ST1;
            const int koff = (kt + 2) * 128;
#pragma unroll
            for (int i = 0; i < 4; ++i) CP_ASYNC16(asw[i] + so, ag[i] + koff);
#pragma unroll
            for (int i = 0; i < 4; ++i) CP_ASYNC16(bsw[i] + so, bg[i] + koff);
            CP_COMMIT();
        }

        const uint32_t st = (uint32_t)cur * ST1;
#pragma unroll
        for (int s = 0; s < 4; ++s) {
            uint32_t af[4][4], bf[2][4];
#pragma unroll
            for (int i = 0; i < 4; ++i) {
                uint32_t addr = sb + st + a_rb[i] +
                                ((uint32_t)((2 * s + a_hi) ^ a_r7[i]) << 4);
                LDSM_X4(af[i], addr);
            }
#pragma unroll
            for (int g = 0; g < 2; ++g) {
                uint32_t addr = sb + st + 16384u + b_rb[g] +
                                ((uint32_t)((2 * s + b_hi) ^ b_r7[g]) << 4);
                LDSM_X4(bf[g], addr);
            }
#pragma unroll
            for (int i = 0; i < 4; ++i)
#pragma unroll
                for (int n = 0; n < 4; ++n)
                    MMA_BF16(acc[i][n], af[i], bf[n >> 1][(n & 1) * 2], bf[n >> 1][(n & 1) * 2 + 1]);
        }
        cur = (cur == 2) ? 0 : cur + 1;
        nxt = (nxt == 2) ? 0 : nxt + 1;
    }

    // ---- fused epilogue: leaky + conv2 reduce over p = row&3 (shfl.bfly) ----
    const int gid = lane >> 2, tig = lane & 3;
    const int p = gid & 3;
    const int grb = (row0 + wm * 64) >> 2;
#pragma unroll
    for (int i = 0; i < 4; ++i) {
        int gr_lo = grb + i * 4 + (gid >> 2);
#pragma unroll
        for (int n = 0; n < 4; ++n) {
            int c = col0 + wn * 32 + n * 8 + tig * 2;
            bool cv = (c < Ncols);
            float b0 = cv ? bias[c] : 0.f,            b1 = cv ? bias[c + 1] : 0.f;
            float w0 = cv ? w2[p * Ncols + c] : 0.f,  w1 = cv ? w2[p * Ncols + c + 1] : 0.f;
            float y0 = lrelu(acc[i][n][0] + b0) * w0;
            float y1 = lrelu(acc[i][n][1] + b1) * w1;
            float y2 = lrelu(acc[i][n][2] + b0) * w0;
            float y3 = lrelu(acc[i][n][3] + b1) * w1;
            y0 += __shfl_xor_sync(0xffffffffu, y0, 4);
            y1 += __shfl_xor_sync(0xffffffffu, y1, 4);
            y2 += __shfl_xor_sync(0xffffffffu, y2, 4);
            y3 += __shfl_xor_sync(0xffffffffu, y3, 4);
            y0 += __shfl_xor_sync(0xffffffffu, y0, 8);
            y1 += __shfl_xor_sync(0xffffffffu, y1, 8);
            y2 += __shfl_xor_sync(0xffffffffu, y2, 8);
            y3 += __shfl_xor_sync(0xffffffffu, y3, 8);
            if (p == 0) {
                __nv_bfloat162 lo = __floats2bfloat162_rn(y0, y1);
                __nv_bfloat162 hi = __floats2bfloat162_rn(y2, y3);
                *(uint32_t*)(g2out + (size_t)gr_lo * g2stride + c)       = *(uint32_t*)&lo;
                *(uint32_t*)(g2out + (size_t)(gr_lo + 2) * g2stride + c) = *(uint32_t*)&hi;
            }
        }
    }
}

// ================= GEMM2: CTA 64x64, 128 threads, warp 32x32, 3-stage (proven) =================
constexpr int ST2   = 16384;
constexpr int SMEM2 = 3 * ST2;

__global__ __launch_bounds__(128, 4)
void gemm2_small(const __nv_bfloat16* __restrict__ A, const __nv_bfloat16* __restrict__ Bt,
                 const float* __restrict__ bias, float* __restrict__ C,
                 int Ncols, int lda, int ldb, int ntiles) {
    extern __shared__ char smem[];
    const uint32_t sb = smem_u32(smem);
    const int tid  = threadIdx.x;
    const int lane = tid & 31, warp = tid >> 5;
    const int wm = warp & 1, wn = warp >> 1;
    const int row0 = blockIdx.y * 64;
    const int col0 = blockIdx.x * 64;

    const int crow = tid >> 3, ccol = tid & 7;
    const char* ag0 = (const char*)(A  + (size_t)(row0 + crow) * lda) + ccol * 16;
    const char* bg0 = (const char*)(Bt + (size_t)(col0 + crow) * ldb) + ccol * 16;
    const uint32_t csw = (uint32_t)(crow * 128 + ((ccol ^ (crow & 7)) << 4));
    const uint32_t asw0 = sb + csw;
    const uint32_t bsw0 = sb + 8192u + csw;
    const size_t astep = (size_t)16 * lda * 2;
    const size_t bstep = (size_t)16 * ldb * 2;

    uint32_t a_rb[2]; int a_r7[2];
    {
        int rc = wm * 32 + (lane & 15);
#pragma unroll
        for (int i = 0; i < 2; ++i) { int r = rc + i * 16; a_rb[i] = (uint32_t)r << 7; a_r7[i] = r & 7; }
    }
    const int a_hi = lane >> 4;
    uint32_t b_rb[2]; int b_r7[2];
    {
        int rc = wn * 32 + ((lane >> 4) << 3) + (lane & 7);
#pragma unroll
        for (int g = 0; g < 2; ++g) { int r = rc + g * 16; b_rb[g] = (uint32_t)r << 7; b_r7[g] = r & 7; }
    }
    const int b_hi = (lane >> 3) & 1;

    float acc[2][4][4] = {};

#pragma unroll
    for (int s = 0; s < 2; ++s) {
        const uint32_t so = (uint32_t)s * ST2;
        const int koff = s * 128;
#pragma unroll
        for (int i = 0; i < 4; ++i) CP_ASYNC16(asw0 + so + 2048u * i, ag0 + koff + i * astep);
#pragma unroll
        for (int i = 0; i < 4; ++i) CP_ASYNC16(bsw0 + so + 2048u * i, bg0 + koff + i * bstep);
        CP_COMMIT();
    }

    int cur = 0, nxt = 2;
    for (int kt = 0; kt < ntiles; ++kt) {
        if (kt + 1 < ntiles) { CP_WAIT1(); } else { CP_WAIT0(); }
        __syncthreads();

        if (kt + 2 < ntiles) {
            const uint32_t so = (uint32_t)nxt * ST2;
            const int koff = (kt + 2) * 128;
#pragma unroll
            for (int i = 0; i < 4; ++i) CP_ASYNC16(asw0 + so + 2048u * i, ag0 + koff + i * astep);
#pragma unroll
            for (int i = 0; i < 4; ++i) CP_ASYNC16(bsw0 + so + 2048u * i, bg0 + koff + i * bstep);
            CP_COMMIT();
        }

        const uint32_t st = (uint32_t)cur * ST2;
#pragma unroll
        for (int s = 0; s < 4; ++s) {
            uint32_t af[2][4], bf[2][4];
#pragma unroll
            for (int i = 0; i < 2; ++i) {
                uint32_t addr = sb + st + a_rb[i] +
                                ((uint32_t)((2 * s + a_hi) ^ a_r7[i]) << 4);
                LDSM_X4(af[i], addr);
            }
#pragma unroll
            for (int g = 0; g < 2; ++g) {
                uint32_t addr = sb + st + 8192u + b_rb[g] +
                                ((uint32_t)((2 * s + b_hi) ^ b_r7[g]) << 4);
                LDSM_X4(bf[g], addr);
            }
#pragma unroll
            for (int i = 0; i < 2; ++i)
#pragma unroll
                for (int n = 0; n < 4; ++n)
                    MMA_BF16(acc[i][n], af[i], bf[n >> 1][(n & 1) * 2], bf[n >> 1][(n & 1) * 2 + 1]);
        }
        cur = (cur == 2) ? 0 : cur + 1;
        nxt = (nxt == 2) ? 0 : nxt + 1;
    }

    const int gid = lane >> 2, tig = lane & 3;
#pragma unroll
    for (int i = 0; i < 2; ++i) {
        int r_lo = row0 + wm * 32 + i * 16 + gid;
        int r_hi = r_lo + 8;
#pragma unroll
        for (int n = 0; n < 4; ++n) {
            int c = col0 + wn * 32 + n * 8 + tig * 2;
            if (c < Ncols) {
                float b0 = bias[c], b1 = bias[c + 1];
                float v0 = lrelu(acc[i][n][0] + b0), v1 = lrelu(acc[i][n][1] + b1);
                float v2 = lrelu(acc[i][n][2] + b0), v3 = lrelu(acc[i][n][3] + b1);
                *(float2*)(C + (size_t)r_lo * Ncols + c) = make_float2(v0, v1);
                *(float2*)(C + (size_t)r_hi * Ncols + c) = make_float2(v2, v3);
            }
        }
    }
}

// ---------------- launcher: halved pipeline with legal capture fork/join ----------------
static cudaStream_t g_s1 = nullptr;
static cudaEvent_t  g_evF = nullptr, g_evA = nullptr, g_evB = nullptr,
                    g_evG1A = nullptr, g_evJ = nullptr;

extern "C" void kernel_launch(void* const* d_in, const int* in_sizes, int n_in,
                              void* d_out, int out_size) {
    const float* x   = (const float*)d_in[0];
    const float* c1w = (const float*)d_in[1];   // conv1_w [4,2048]
    const float* p1W = (const float*)d_in[4];   // prop1_W [2048,1100]
    const float* p1B = (const float*)d_in[5];   // prop1_B [1100]
    const float* c2w = (const float*)d_in[6];   // conv2_w [4,1100]
    const float* p2W = (const float*)d_in[9];   // prop2_W [1100,512]
    const float* p2B = (const float*)d_in[10];  // prop2_B [512]
    float* out = (float*)d_out;                 // [2048,512]
    // d_in[2,3,7,8]: pool weights — dead code (adjacency normalizes to identity)

    __nv_bfloat16 *g1, *g2, *bt1, *bt2;
    cudaGetSymbolAddress((void**)&g1,  g_g1);
    cudaGetSymbolAddress((void**)&g2,  g_g2);
    cudaGetSymbolAddress((void**)&bt1, g_bt1);
    cudaGetSymbolAddress((void**)&bt2, g_bt2);

    if (!g_s1) {    // first call is the uncaptured correctness run: safe to create here
        cudaStreamCreateWithFlags(&g_s1, cudaStreamNonBlocking);
        cudaEventCreateWithFlags(&g_evF,   cudaEventDisableTiming);
        cudaEventCreateWithFlags(&g_evA,   cudaEventDisableTiming);
        cudaEventCreateWithFlags(&g_evB,   cudaEventDisableTiming);
        cudaEventCreateWithFlags(&g_evG1A, cudaEventDisableTiming);
        cudaEventCreateWithFlags(&g_evJ,   cudaEventDisableTiming);
        cudaFuncSetAttribute(gemm1_fused, cudaFuncAttributeMaxDynamicSharedMemorySize, SMEM1);
        cudaFuncSetAttribute(gemm2_small, cudaFuncAttributeMaxDynamicSharedMemorySize, SMEM2);
    }

    const long convTotH = (long)MH * (Fdim / 8);
    const int  convBlkH = (int)((convTotH + 255) / 256);

    // fork FROM the capture stream: side stream joins the capture via evF
    cudaEventRecord(g_evF, 0);
    cudaStreamWaitEvent(g_s1, g_evF, 0);

    // s1: weight transposes (parallel with conv1-A)
    transpose_bf16<<<dim3(Fdim / 32, N1PAD / 32), dim3(32, 8), 0, g_s1>>>(
        p1W, bt1, Fdim, HID, Fdim, N1PAD);
    transpose_bf16<<<dim3(K2PAD / 32, NCLS / 32), dim3(32, 8), 0, g_s1>>>(
        p2W, bt2, HID, NCLS, K2PAD, NCLS);

    // s0: conv1 halves
    node_conv4_bf16<Fdim><<<convBlkH, 256>>>(x, c1w, g1, MH);
    cudaEventRecord(g_evA, 0);
    node_conv4_bf16<Fdim><<<convBlkH, 256>>>(x + (size_t)MH * 4 * Fdim, c1w,
                                             g1 + (size_t)MH * Fdim, MH);
    cudaEventRecord(g_evB, 0);

    // s1: GEMM1 halves as conv halves land (each 288 CTAs = one wave)
    cudaStreamWaitEvent(g_s1, g_evA, 0);
    gemm1_fused<<<dim3(N1PAD / 128, MH / 128), 256, SMEM1, g_s1>>>(
        g1, bt1, p1B, c2w, g2, HID, Fdim, Fdim, Fdim / 64, K2PAD);
    cudaEventRecord(g_evG1A, g_s1);

    cudaStreamWaitEvent(g_s1, g_evB, 0);
    gemm1_fused<<<dim3(N1PAD / 128, MH / 128), 256, SMEM1, g_s1>>>(
        g1 + (size_t)MH * Fdim, bt1, p1B, c2w, g2 + (size_t)(MH / 4) * K2PAD,
        HID, Fdim, Fdim, Fdim / 64, K2PAD);

    // s0: GEMM2 half A (rows 0..1023) fills GEMM1-B's tail
    cudaStreamWaitEvent(0, g_evG1A, 0);
    gemm2_small<<<dim3(NCLS / 64, (M2 / 2) / 64), 128, SMEM2>>>(
        g2, bt2, p2B, out, NCLS, K2PAD, K2PAD, K2PAD / 64);

    // s1: GEMM2 half B (rows 1024..2047) after GEMM1-B
    gemm2_small<<<dim3(NCLS / 64, (M2 / 2) / 64), 128, SMEM2, g_s1>>>(
        g2 + (size_t)(M2 / 2) * K2PAD, bt2, p2B, out + (size_t)(M2 / 2) * NCLS,
        NCLS, K2PAD, K2PAD, K2PAD / 64);

    // join side stream back into the capture stream
    cudaEventRecord(g_evJ, g_s1);
    cudaStreamWaitEvent(0, g_evJ, 0);
}

// round 14
// speedup vs baseline: 1.0445x; 1.0445x over previous
#include <cuda_runtime.h>
#include <cuda_bf16.h>
#include <cstdint>

// ---------------- problem constants ----------------
constexpr int Fdim = 2048;
constexpr int HID  = 1100;
constexpr int NCLS = 512;
constexpr int M1   = 8192;     // 64 * 512/4
constexpr int M2   = 2048;     // M1 / 4
constexpr int N1PAD = 1152;    // HID padded to mult of 128 (GEMM1 N)
constexpr int K2PAD = 1152;    // = N1PAD; GEMM2 K padding

// ---------------- scratch (no cudaMalloc allowed) ----------------
__device__ __align__(16) __nv_bfloat16 g_g1 [M1 * Fdim];     // conv1 out (bf16)  32 MB
__device__ __align__(16) __nv_bfloat16 g_g2 [M2 * K2PAD];    // fused conv2 out   4.7 MB
__device__ __align__(16) __nv_bfloat16 g_bt1[N1PAD * Fdim];  // prop1_W^T bf16    4.7 MB
__device__ __align__(16) __nv_bfloat16 g_bt2[NCLS * K2PAD];  // prop2_W^T bf16    1.2 MB

// ---------------- helpers ----------------
__device__ __forceinline__ uint32_t smem_u32(const void* p) {
    uint32_t a;
    asm("{ .reg .u64 t; cvta.to.shared.u64 t, %1; cvt.u32.u64 %0, t; }" : "=r"(a) : "l"(p));
    return a;
}

#define CP_ASYNC16(saddr, gptr) \
    asm volatile("cp.async.cg.shared.global [%0], [%1], 16;" :: "r"(saddr), "l"(gptr))
#define CP_COMMIT()  asm volatile("cp.async.commit_group;" ::: "memory")
#define CP_WAIT1()   asm volatile("cp.async.wait_group 1;" ::: "memory")
#define CP_WAIT0()   asm volatile("cp.async.wait_group 0;" ::: "memory")

#define LDSM_X4(r, addr) \
    asm volatile("ldmatrix.sync.aligned.m8n8.x4.shared.b16 {%0,%1,%2,%3}, [%4];" \
        : "=r"((r)[0]), "=r"((r)[1]), "=r"((r)[2]), "=r"((r)[3]) : "r"(addr))

#define MMA_BF16(c, a, b0, b1) \
    asm volatile("mma.sync.aligned.m16n8k16.row.col.f32.bf16.bf16.f32 " \
        "{%0,%1,%2,%3}, {%4,%5,%6,%7}, {%8,%9}, {%0,%1,%2,%3};" \
        : "+f"((c)[0]), "+f"((c)[1]), "+f"((c)[2]), "+f"((c)[3]) \
        : "r"((a)[0]), "r"((a)[1]), "r"((a)[2]), "r"((a)[3]), "r"(b0), "r"(b1))

__device__ __forceinline__ float lrelu(float v) { return (v >= 0.f) ? v : 0.01f * v; }

// ---------------- node conv: two coalesced column panels per thread ----------------
// out[r, :] = bf16( sum_p x[4r+p, :] * w[p, :] ).  Thread handles cols [4j,4j+4) and
// [4(j+F8),4(j+F8)+4): every warp LDG request is 512B contiguous (full lines).
template<int FD>
__global__ void node_conv4_bf16(const float* __restrict__ x, const float* __restrict__ w,
                                __nv_bfloat16* __restrict__ out, int rows) {
    constexpr int F4 = FD / 4;      // float4 per row
    constexpr int F8 = F4 / 2;      // panel width in float4
    long idx = (long)blockIdx.x * blockDim.x + threadIdx.x;
    if (idx >= (long)rows * F8) return;
    int r = (int)(idx / F8);
    int j = (int)(idx % F8);
    const float4* x4 = (const float4*)x;
    const float4* w4 = (const float4*)w;
    float4 a0 = make_float4(0.f, 0.f, 0.f, 0.f);
    float4 a1 = make_float4(0.f, 0.f, 0.f, 0.f);
#pragma unroll
    for (int p = 0; p < 4; ++p) {
        const float4* xr = x4 + (long)(4 * r + p) * F4;
        const float4* wr = w4 + p * F4;
        float4 xv0 = xr[j],      wv0 = wr[j];
        float4 xv1 = xr[j + F8], wv1 = wr[j + F8];
        a0.x = fmaf(xv0.x, wv0.x, a0.x); a0.y = fmaf(xv0.y, wv0.y, a0.y);
        a0.z = fmaf(xv0.z, wv0.z, a0.z); a0.w = fmaf(xv0.w, wv0.w, a0.w);
        a1.x = fmaf(xv1.x, wv1.x, a1.x); a1.y = fmaf(xv1.y, wv1.y, a1.y);
        a1.z = fmaf(xv1.z, wv1.z, a1.z); a1.w = fmaf(xv1.w, wv1.w, a1.w);
    }
    __nv_bfloat162 b0 = __floats2bfloat162_rn(a0.x, a0.y);
    __nv_bfloat162 b1 = __floats2bfloat162_rn(a0.z, a0.w);
    __nv_bfloat162 b2 = __floats2bfloat162_rn(a1.x, a1.y);
    __nv_bfloat162 b3 = __floats2bfloat162_rn(a1.z, a1.w);
    uint2 v0, v1;
    v0.x = *(uint32_t*)&b0; v0.y = *(uint32_t*)&b1;
    v1.x = *(uint32_t*)&b2; v1.y = *(uint32_t*)&b3;
    uint2* o2 = (uint2*)out + (long)r * F4;
    o2[j]      = v0;
    o2[j + F8] = v1;
}

// ---------------- transpose + bf16 round + zero pad:  W[K][N] -> Bt[Npad][Kpad] ----------------
__global__ void transpose_bf16(const float* __restrict__ W, __nv_bfloat16* __restrict__ Bt,
                               int K, int N, int Kpad, int Npad) {
    __shared__ float t[32][33];
    int k0 = blockIdx.x * 32, n0 = blockIdx.y * 32;
#pragma unroll
    for (int i = 0; i < 4; ++i) {
        int k = k0 + threadIdx.y + i * 8;
        int n = n0 + threadIdx.x;
        t[threadIdx.y + i * 8][threadIdx.x] = (k < K && n < N) ? W[(long)k * N + n] : 0.f;
    }
    __syncthreads();
#pragma unroll
    for (int i = 0; i < 4; ++i) {
        int n = n0 + threadIdx.y + i * 8;
        int k = k0 + threadIdx.x;
        if (n < Npad && k < Kpad)
            Bt[(long)n * Kpad + k] = __float2bfloat16_rn(t[threadIdx.x][threadIdx.y + i * 8]);
    }
}

// ================= GEMM1 (fused conv2): CTA 128x128, 256 thr, warp 64x32, 3-stage (proven) =================
constexpr int ST1   = 32768;               // A 16KB + B 16KB
constexpr int SMEM1 = 3 * ST1;             // 98304 B

__global__ __launch_bounds__(256, 2)
void gemm1_fused(const __nv_bfloat16* __restrict__ A, const __nv_bfloat16* __restrict__ Bt,
                 const float* __restrict__ bias, const float* __restrict__ w2,
                 __nv_bfloat16* __restrict__ g2out,
                 int Ncols, int lda, int ldb, int ntiles, int g2stride) {
    extern __shared__ char smem[];
    const uint32_t sb = smem_u32(smem);
    const int tid  = threadIdx.x;
    const int lane = tid & 31, warp = tid >> 5;
    const int wm = warp & 1, wn = warp >> 1;
    const int row0 = blockIdx.y * 128;
    const int col0 = blockIdx.x * 128;

    const char* ag[4]; uint32_t asw[4];
    const char* bg[4]; uint32_t bsw[4];
#pragma unroll
    for (int i = 0; i < 4; ++i) {
        int idx = i * 256 + tid;
        int row = idx >> 3, col = idx & 7;
        ag[i]  = (const char*)(A + (size_t)(row0 + row) * lda) + col * 16;
        asw[i] = sb + (uint32_t)(row * 128 + ((col ^ (row & 7)) << 4));
        bg[i]  = (const char*)(Bt + (size_t)(col0 + row) * ldb) + col * 16;
        bsw[i] = sb + 16384u + (uint32_t)(row * 128 + ((col ^ (row & 7)) << 4));
    }

    uint32_t a_rb[4]; int a_r7[4];
    {
        int rc = wm * 64 + (lane & 15);
#pragma unroll
        for (int i = 0; i < 4; ++i) { int r = rc + i * 16; a_rb[i] = (uint32_t)r << 7; a_r7[i] = r & 7; }
    }
    const int a_hi = lane >> 4;
    uint32_t b_rb[2]; int b_r7[2];
    {
        int rc = wn * 32 + ((lane >> 4) << 3) + (lane & 7);
#pragma unroll
        for (int g = 0; g < 2; ++g) { int r = rc + g * 16; b_rb[g] = (uint32_t)r << 7; b_r7[g] = r & 7; }
    }
    const int b_hi = (lane >> 3) & 1;

    float acc[4][4][4] = {};

#pragma unroll
    for (int s = 0; s < 2; ++s) {
        const uint32_t so = (uint32_t)s * ST1;
        const int koff = s * 128;
#pragma unroll
        for (int i = 0; i < 4; ++i) CP_ASYNC16(asw[i] + so, ag[i] + koff);
#pragma unroll
        for (int i = 0; i < 4; ++i) CP_ASYNC16(bsw[i] + so, bg[i] + koff);
        CP_COMMIT();
    }

    int cur = 0, nxt = 2;
    for (int kt = 0; kt < ntiles; ++kt) {
        if (kt + 1 < ntiles) { CP_WAIT1(); } else { CP_WAIT0(); }
        __syncthreads();

        if (kt + 2 < ntiles) {
            const uint32_t so = (uint32_t)nxt * ST1;
            const int koff = (kt + 2) * 128;
#pragma unroll
            for (int i = 0; i < 4; ++i) CP_ASYNC16(asw[i] + so, ag[i] + koff);
#pragma unroll
            for (int i = 0; i < 4; ++i) CP_ASYNC16(bsw[i] + so, bg[i] + koff);
            CP_COMMIT();
        }

        const uint32_t st = (uint32_t)cur * ST1;
#pragma unroll
        for (int s = 0; s < 4; ++s) {
            uint32_t af[4][4], bf[2][4];
#pragma unroll
            for (int i = 0; i < 4; ++i) {
                uint32_t addr = sb + st + a_rb[i] +
                                ((uint32_t)((2 * s + a_hi) ^ a_r7[i]) << 4);
                LDSM_X4(af[i], addr);
            }
#pragma unroll
            for (int g = 0; g < 2; ++g) {
                uint32_t addr = sb + st + 16384u + b_rb[g] +
                                ((uint32_t)((2 * s + b_hi) ^ b_r7[g]) << 4);
                LDSM_X4(bf[g], addr);
            }
#pragma unroll
            for (int i = 0; i < 4; ++i)
#pragma unroll
                for (int n = 0; n < 4; ++n)
                    MMA_BF16(acc[i][n], af[i], bf[n >> 1][(n & 1) * 2], bf[n >> 1][(n & 1) * 2 + 1]);
        }
        cur = (cur == 2) ? 0 : cur + 1;
        nxt = (nxt == 2) ? 0 : nxt + 1;
    }

    // ---- fused epilogue: leaky + conv2 reduce over p = row&3 (shfl.bfly) ----
    const int gid = lane >> 2, tig = lane & 3;
    const int p = gid & 3;
    const int grb = (row0 + wm * 64) >> 2;
#pragma unroll
    for (int i = 0; i < 4; ++i) {
        int gr_lo = grb + i * 4 + (gid >> 2);
#pragma unroll
        for (int n = 0; n < 4; ++n) {
            int c = col0 + wn * 32 + n * 8 + tig * 2;
            bool cv = (c < Ncols);
            float b0 = cv ? bias[c] : 0.f,            b1 = cv ? bias[c + 1] : 0.f;
            float w0 = cv ? w2[p * Ncols + c] : 0.f,  w1 = cv ? w2[p * Ncols + c + 1] : 0.f;
            float y0 = lrelu(acc[i][n][0] + b0) * w0;
            float y1 = lrelu(acc[i][n][1] + b1) * w1;
            float y2 = lrelu(acc[i][n][2] + b0) * w0;
            float y3 = lrelu(acc[i][n][3] + b1) * w1;
            y0 += __shfl_xor_sync(0xffffffffu, y0, 4);
            y1 += __shfl_xor_sync(0xffffffffu, y1, 4);
            y2 += __shfl_xor_sync(0xffffffffu, y2, 4);
            y3 += __shfl_xor_sync(0xffffffffu, y3, 4);
            y0 += __shfl_xor_sync(0xffffffffu, y0, 8);
            y1 += __shfl_xor_sync(0xffffffffu, y1, 8);
            y2 += __shfl_xor_sync(0xffffffffu, y2, 8);
            y3 += __shfl_xor_sync(0xffffffffu, y3, 8);
            if (p == 0) {
                __nv_bfloat162 lo = __floats2bfloat162_rn(y0, y1);
                __nv_bfloat162 hi = __floats2bfloat162_rn(y2, y3);
                *(uint32_t*)(g2out + (size_t)gr_lo * g2stride + c)       = *(uint32_t*)&lo;
                *(uint32_t*)(g2out + (size_t)(gr_lo + 2) * g2stride + c) = *(uint32_t*)&hi;
            }
        }
    }
}

// ================= GEMM2: CTA 64x64, 128 threads, warp 32x32, 3-stage (proven) =================
constexpr int ST2   = 16384;
constexpr int SMEM2 = 3 * ST2;

__global__ __launch_bounds__(128, 4)
void gemm2_small(const __nv_bfloat16* __restrict__ A, const __nv_bfloat16* __restrict__ Bt,
                 const float* __restrict__ bias, float* __restrict__ C,
                 int Ncols, int lda, int ldb, int ntiles) {
    extern __shared__ char smem[];
    const uint32_t sb = smem_u32(smem);
    const int tid  = threadIdx.x;
    const int lane = tid & 31, warp = tid >> 5;
    const int wm = warp & 1, wn = warp >> 1;
    const int row0 = blockIdx.y * 64;
    const int col0 = blockIdx.x * 64;

    const int crow = tid >> 3, ccol = tid & 7;
    const char* ag0 = (const char*)(A  + (size_t)(row0 + crow) * lda) + ccol * 16;
    const char* bg0 = (const char*)(Bt + (size_t)(col0 + crow) * ldb) + ccol * 16;
    const uint32_t csw = (uint32_t)(crow * 128 + ((ccol ^ (crow & 7)) << 4));
    const uint32_t asw0 = sb + csw;
    const uint32_t bsw0 = sb + 8192u + csw;
    const size_t astep = (size_t)16 * lda * 2;
    const size_t bstep = (size_t)16 * ldb * 2;

    uint32_t a_rb[2]; int a_r7[2];
    {
        int rc = wm * 32 + (lane & 15);
#pragma unroll
        for (int i = 0; i < 2; ++i) { int r = rc + i * 16; a_rb[i] = (uint32_t)r << 7; a_r7[i] = r & 7; }
    }
    const int a_hi = lane >> 4;
    uint32_t b_rb[2]; int b_r7[2];
    {
        int rc = wn * 32 + ((lane >> 4) << 3) + (lane & 7);
#pragma unroll
        for (int g = 0; g < 2; ++g) { int r = rc + g * 16; b_rb[g] = (uint32_t)r << 7; b_r7[g] = r & 7; }
    }
    const int b_hi = (lane >> 3) & 1;

    float acc[2][4][4] = {};

#pragma unroll
    for (int s = 0; s < 2; ++s) {
        const uint32_t so = (uint32_t)s * ST2;
        const int koff = s * 128;
#pragma unroll
        for (int i = 0; i < 4; ++i) CP_ASYNC16(asw0 + so + 2048u * i, ag0 + koff + i * astep);
#pragma unroll
        for (int i = 0; i < 4; ++i) CP_ASYNC16(bsw0 + so + 2048u * i, bg0 + koff + i * bstep);
        CP_COMMIT();
    }

    int cur = 0, nxt = 2;
    for (int kt = 0; kt < ntiles; ++kt) {
        if (kt + 1 < ntiles) { CP_WAIT1(); } else { CP_WAIT0(); }
        __syncthreads();

        if (kt + 2 < ntiles) {
            const uint32_t so = (uint32_t)nxt * ST2;
            const int koff = (kt + 2) * 128;
#pragma unroll
            for (int i = 0; i < 4; ++i) CP_ASYNC16(asw0 + so + 2048u * i, ag0 + koff + i * astep);
#pragma unroll
            for (int i = 0; i < 4; ++i) CP_ASYNC16(bsw0 + so + 2048u * i, bg0 + koff + i * bstep);
            CP_COMMIT();
        }

        const uint32_t st = (uint32_t)cur * ST2;
#pragma unroll
        for (int s = 0; s < 4; ++s) {
            uint32_t af[2][4], bf[2][4];
#pragma unroll
            for (int i = 0; i < 2; ++i) {
                uint32_t addr = sb + st + a_rb[i] +
                                ((uint32_t)((2 * s + a_hi) ^ a_r7[i]) << 4);
                LDSM_X4(af[i], addr);
            }
#pragma unroll
            for (int g = 0; g < 2; ++g) {
                uint32_t addr = sb + st + 8192u + b_rb[g] +
                                ((uint32_t)((2 * s + b_hi) ^ b_r7[g]) << 4);
                LDSM_X4(bf[g], addr);
            }
#pragma unroll
            for (int i = 0; i < 2; ++i)
#pragma unroll
                for (int n = 0; n < 4; ++n)
                    MMA_BF16(acc[i][n], af[i], bf[n >> 1][(n & 1) * 2], bf[n >> 1][(n & 1) * 2 + 1]);
        }
        cur = (cur == 2) ? 0 : cur + 1;
        nxt = (nxt == 2) ? 0 : nxt + 1;
    }

    const int gid = lane >> 2, tig = lane & 3;
#pragma unroll
    for (int i = 0; i < 2; ++i) {
        int r_lo = row0 + wm * 32 + i * 16 + gid;
        int r_hi = r_lo + 8;
#pragma unroll
        for (int n = 0; n < 4; ++n) {
            int c = col0 + wn * 32 + n * 8 + tig * 2;
            if (c < Ncols) {
                float b0 = bias[c], b1 = bias[c + 1];
                float v0 = lrelu(acc[i][n][0] + b0), v1 = lrelu(acc[i][n][1] + b1);
                float v2 = lrelu(acc[i][n][2] + b0), v3 = lrelu(acc[i][n][3] + b1);
                *(float2*)(C + (size_t)r_lo * Ncols + c) = make_float2(v0, v1);
                *(float2*)(C + (size_t)r_hi * Ncols + c) = make_float2(v2, v3);
            }
        }
    }
}

// ---------------- launcher: R12 linear chain + legal fork for transposes ----------------
static cudaStream_t g_s1 = nullptr;
static cudaEvent_t  g_evF = nullptr, g_evT = nullptr;

extern "C" void kernel_launch(void* const* d_in, const int* in_sizes, int n_in,
                              void* d_out, int out_size) {
    const float* x   = (const float*)d_in[0];
    const float* c1w = (const float*)d_in[1];   // conv1_w [4,2048]
    const float* p1W = (const float*)d_in[4];   // prop1_W [2048,1100]
    const float* p1B = (const float*)d_in[5];   // prop1_B [1100]
    const float* c2w = (const float*)d_in[6];   // conv2_w [4,1100]
    const float* p2W = (const float*)d_in[9];   // prop2_W [1100,512]
    const float* p2B = (const float*)d_in[10];  // prop2_B [512]
    float* out = (float*)d_out;                 // [2048,512]
    // d_in[2,3,7,8]: pool weights — dead code (adjacency normalizes to identity)

    __nv_bfloat16 *g1, *g2, *bt1, *bt2;
    cudaGetSymbolAddress((void**)&g1,  g_g1);
    cudaGetSymbolAddress((void**)&g2,  g_g2);
    cudaGetSymbolAddress((void**)&bt1, g_bt1);
    cudaGetSymbolAddress((void**)&bt2, g_bt2);

    if (!g_s1) {    // first call is the uncaptured correctness run: safe to create here
        cudaStreamCreateWithFlags(&g_s1, cudaStreamNonBlocking);
        cudaEventCreateWithFlags(&g_evF, cudaEventDisableTiming);
        cudaEventCreateWithFlags(&g_evT, cudaEventDisableTiming);
        cudaFuncSetAttribute(gemm1_fused, cudaFuncAttributeMaxDynamicSharedMemorySize, SMEM1);
        cudaFuncSetAttribute(gemm2_small, cudaFuncAttributeMaxDynamicSharedMemorySize, SMEM2);
    }

    // fork FROM the capture stream: side stream joins the capture via evF
    cudaEventRecord(g_evF, 0);
    cudaStreamWaitEvent(g_s1, g_evF, 0);

    // side stream (in-graph): weight transposes, parallel with conv1
    transpose_bf16<<<dim3(Fdim / 32, N1PAD / 32), dim3(32, 8), 0, g_s1>>>(
        p1W, bt1, Fdim, HID, Fdim, N1PAD);
    transpose_bf16<<<dim3(K2PAD / 32, NCLS / 32), dim3(32, 8), 0, g_s1>>>(
        p2W, bt2, HID, NCLS, K2PAD, NCLS);
    cudaEventRecord(g_evT, g_s1);

    // capture stream: conv1 -> (join) -> GEMM1(+fused conv2) -> GEMM2
    {
        long total = (long)M1 * (Fdim / 8);
        node_conv4_bf16<Fdim><<<(int)((total + 255) / 256), 256>>>(x, c1w, g1, M1);
    }
    cudaStreamWaitEvent(0, g_evT, 0);
    gemm1_fused<<<dim3(N1PAD / 128, M1 / 128), 256, SMEM1>>>(
        g1, bt1, p1B, c2w, g2, HID, Fdim, Fdim, Fdim / 64, K2PAD);

    gemm2_small<<<dim3(NCLS / 64, M2 / 64), 128, SMEM2>>>(
        g2, bt2, p2B, out, NCLS, K2PAD, K2PAD, K2PAD / 64);
}

// round 15
// speedup vs baseline: 1.0633x; 1.0181x over previous
#include <cuda_runtime.h>
#include <cuda_bf16.h>
#include <cstdint>

// ---------------- problem constants ----------------
constexpr int Fdim = 2048;
constexpr int HID  = 1100;
constexpr int NCLS = 512;
constexpr int M1   = 8192;     // 64 * 512/4
constexpr int M2   = 2048;     // M1 / 4
constexpr int N1PAD = 1152;    // HID padded to mult of 128 (GEMM1 N)
constexpr int K2PAD = 1152;    // = N1PAD; GEMM2 K padding

// ---------------- scratch (no cudaMalloc allowed) ----------------
__device__ __align__(16) __nv_bfloat16 g_g1 [M1 * Fdim];     // conv1 out (bf16)  32 MB
__device__ __align__(16) __nv_bfloat16 g_g2 [M2 * K2PAD];    // fused conv2 out   4.7 MB
__device__ __align__(16) __nv_bfloat16 g_bt1[N1PAD * Fdim];  // prop1_W^T bf16    4.7 MB
__device__ __align__(16) __nv_bfloat16 g_bt2[NCLS * K2PAD];  // prop2_W^T bf16    1.2 MB

// ---------------- helpers ----------------
__device__ __forceinline__ uint32_t smem_u32(const void* p) {
    uint32_t a;
    asm("{ .reg .u64 t; cvta.to.shared.u64 t, %1; cvt.u32.u64 %0, t; }" : "=r"(a) : "l"(p));
    return a;
}

#define CP_ASYNC16(saddr, gptr) \
    asm volatile("cp.async.cg.shared.global [%0], [%1], 16;" :: "r"(saddr), "l"(gptr))
#define CP_COMMIT()  asm volatile("cp.async.commit_group;" ::: "memory")
#define CP_WAIT1()   asm volatile("cp.async.wait_group 1;" ::: "memory")
#define CP_WAIT0()   asm volatile("cp.async.wait_group 0;" ::: "memory")

#define LDSM_X4(r, addr) \
    asm volatile("ldmatrix.sync.aligned.m8n8.x4.shared.b16 {%0,%1,%2,%3}, [%4];" \
        : "=r"((r)[0]), "=r"((r)[1]), "=r"((r)[2]), "=r"((r)[3]) : "r"(addr))

#define MMA_BF16(c, a, b0, b1) \
    asm volatile("mma.sync.aligned.m16n8k16.row.col.f32.bf16.bf16.f32 " \
        "{%0,%1,%2,%3}, {%4,%5,%6,%7}, {%8,%9}, {%0,%1,%2,%3};" \
        : "+f"((c)[0]), "+f"((c)[1]), "+f"((c)[2]), "+f"((c)[3]) \
        : "r"((a)[0]), "r"((a)[1]), "r"((a)[2]), "r"((a)[3]), "r"(b0), "r"(b1))

__device__ __forceinline__ float lrelu(float v) { return (v >= 0.f) ? v : 0.01f * v; }

// ---------------- node conv: two coalesced column panels per thread ----------------
template<int FD>
__global__ void node_conv4_bf16(const float* __restrict__ x, const float* __restrict__ w,
                                __nv_bfloat16* __restrict__ out, int rows) {
    constexpr int F4 = FD / 4;      // float4 per row
    constexpr int F8 = F4 / 2;      // panel width in float4
    long idx = (long)blockIdx.x * blockDim.x + threadIdx.x;
    if (idx < (long)rows * F8) {
        int r = (int)(idx / F8);
        int j = (int)(idx % F8);
        const float4* x4 = (const float4*)x;
        const float4* w4 = (const float4*)w;
        float4 a0 = make_float4(0.f, 0.f, 0.f, 0.f);
        float4 a1 = make_float4(0.f, 0.f, 0.f, 0.f);
#pragma unroll
        for (int p = 0; p < 4; ++p) {
            const float4* xr = x4 + (long)(4 * r + p) * F4;
            const float4* wr = w4 + p * F4;
            float4 xv0 = xr[j],      wv0 = wr[j];
            float4 xv1 = xr[j + F8], wv1 = wr[j + F8];
            a0.x = fmaf(xv0.x, wv0.x, a0.x); a0.y = fmaf(xv0.y, wv0.y, a0.y);
            a0.z = fmaf(xv0.z, wv0.z, a0.z); a0.w = fmaf(xv0.w, wv0.w, a0.w);
            a1.x = fmaf(xv1.x, wv1.x, a1.x); a1.y = fmaf(xv1.y, wv1.y, a1.y);
            a1.z = fmaf(xv1.z, wv1.z, a1.z); a1.w = fmaf(xv1.w, wv1.w, a1.w);
        }
        __nv_bfloat162 b0 = __floats2bfloat162_rn(a0.x, a0.y);
        __nv_bfloat162 b1 = __floats2bfloat162_rn(a0.z, a0.w);
        __nv_bfloat162 b2 = __floats2bfloat162_rn(a1.x, a1.y);
        __nv_bfloat162 b3 = __floats2bfloat162_rn(a1.z, a1.w);
        uint2 v0, v1;
        v0.x = *(uint32_t*)&b0; v0.y = *(uint32_t*)&b1;
        v1.x = *(uint32_t*)&b2; v1.y = *(uint32_t*)&b3;
        uint2* o2 = (uint2*)out + (long)r * F4;
        o2[j]      = v0;
        o2[j + F8] = v1;
    }
    cudaTriggerProgrammaticLaunchCompletion();
}

// ---------------- transpose + bf16 round + zero pad:  W[K][N] -> Bt[Npad][Kpad] ----------------
__global__ void transpose_bf16(const float* __restrict__ W, __nv_bfloat16* __restrict__ Bt,
                               int K, int N, int Kpad, int Npad) {
    __shared__ float t[32][33];
    int k0 = blockIdx.x * 32, n0 = blockIdx.y * 32;
#pragma unroll
    for (int i = 0; i < 4; ++i) {
        int k = k0 + threadIdx.y + i * 8;
        int n = n0 + threadIdx.x;
        t[threadIdx.y + i * 8][threadIdx.x] = (k < K && n < N) ? W[(long)k * N + n] : 0.f;
    }
    __syncthreads();
#pragma unroll
    for (int i = 0; i < 4; ++i) {
        int n = n0 + threadIdx.y + i * 8;
        int k = k0 + threadIdx.x;
        if (n < Npad && k < Kpad)
            Bt[(long)n * Kpad + k] = __float2bfloat16_rn(t[threadIdx.x][threadIdx.y + i * 8]);
    }
}

// ================= GEMM1 (fused conv2): CTA 128x128, 256 thr, warp 64x32, 3-stage (proven) =================
constexpr int ST1   = 32768;               // A 16KB + B 16KB
constexpr int SMEM1 = 3 * ST1;             // 98304 B

__global__ __launch_bounds__(256, 2)
void gemm1_fused(const __nv_bfloat16* __restrict__ A, const __nv_bfloat16* __restrict__ Bt,
                 const float* __restrict__ bias, const float* __restrict__ w2,
                 __nv_bfloat16* __restrict__ g2out,
                 int Ncols, int lda, int ldb, int ntiles, int g2stride) {
    extern __shared__ char smem[];
    const uint32_t sb = smem_u32(smem);
    const int tid  = threadIdx.x;
    const int lane = tid & 31, warp = tid >> 5;
    const int wm = warp & 1, wn = warp >> 1;
    const int row0 = blockIdx.y * 128;
    const int col0 = blockIdx.x * 128;

    const char* ag[4]; uint32_t asw[4];
    const char* bg[4]; uint32_t bsw[4];
#pragma unroll
    for (int i = 0; i < 4; ++i) {
        int idx = i * 256 + tid;
        int row = idx >> 3, col = idx & 7;
        ag[i]  = (const char*)(A + (size_t)(row0 + row) * lda) + col * 16;
        asw[i] = sb + (uint32_t)(row * 128 + ((col ^ (row & 7)) << 4));
        bg[i]  = (const char*)(Bt + (size_t)(col0 + row) * ldb) + col * 16;
        bsw[i] = sb + 16384u + (uint32_t)(row * 128 + ((col ^ (row & 7)) << 4));
    }

    uint32_t a_rb[4]; int a_r7[4];
    {
        int rc = wm * 64 + (lane & 15);
#pragma unroll
        for (int i = 0; i < 4; ++i) { int r = rc + i * 16; a_rb[i] = (uint32_t)r << 7; a_r7[i] = r & 7; }
    }
    const int a_hi = lane >> 4;
    uint32_t b_rb[2]; int b_r7[2];
    {
        int rc = wn * 32 + ((lane >> 4) << 3) + (lane & 7);
#pragma unroll
        for (int g = 0; g < 2; ++g) { int r = rc + g * 16; b_rb[g] = (uint32_t)r << 7; b_r7[g] = r & 7; }
    }
    const int b_hi = (lane >> 3) & 1;

    float acc[4][4][4] = {};

    // PDL: launched during producer tail; block here until producer data is visible
    cudaGridDependencySynchronize();

#pragma unroll
    for (int s = 0; s < 2; ++s) {
        const uint32_t so = (uint32_t)s * ST1;
        const int koff = s * 128;
#pragma unroll
        for (int i = 0; i < 4; ++i) CP_ASYNC16(asw[i] + so, ag[i] + koff);
#pragma unroll
        for (int i = 0; i < 4; ++i) CP_ASYNC16(bsw[i] + so, bg[i] + koff);
        CP_COMMIT();
    }

    int cur = 0, nxt = 2;
    for (int kt = 0; kt < ntiles; ++kt) {
        if (kt + 1 < ntiles) { CP_WAIT1(); } else { CP_WAIT0(); }
        __syncthreads();

        if (kt + 2 < ntiles) {
            const uint32_t so = (uint32_t)nxt * ST1;
            const int koff = (kt + 2) * 128;
#pragma unroll
            for (int i = 0; i < 4; ++i) CP_ASYNC16(asw[i] + so, ag[i] + koff);
#pragma unroll
            for (int i = 0; i < 4; ++i) CP_ASYNC16(bsw[i] + so, bg[i] + koff);
            CP_COMMIT();
        }

        const uint32_t st = (uint32_t)cur * ST1;
#pragma unroll
        for (int s = 0; s < 4; ++s) {
            uint32_t af[4][4], bf[2][4];
#pragma unroll
            for (int i = 0; i < 4; ++i) {
                uint32_t addr = sb + st + a_rb[i] +
                                ((uint32_t)((2 * s + a_hi) ^ a_r7[i]) << 4);
                LDSM_X4(af[i], addr);
            }
#pragma unroll
            for (int g = 0; g < 2; ++g) {
                uint32_t addr = sb + st + 16384u + b_rb[g] +
                                ((uint32_t)((2 * s + b_hi) ^ b_r7[g]) << 4);
                LDSM_X4(bf[g], addr);
            }
#pragma unroll
            for (int i = 0; i < 4; ++i)
#pragma unroll
                for (int n = 0; n < 4; ++n)
                    MMA_BF16(acc[i][n], af[i], bf[n >> 1][(n & 1) * 2], bf[n >> 1][(n & 1) * 2 + 1]);
        }
        cur = (cur == 2) ? 0 : cur + 1;
        nxt = (nxt == 2) ? 0 : nxt + 1;
    }

    // ---- fused epilogue: leaky + conv2 reduce over p = row&3 (shfl.bfly) ----
    const int gid = lane >> 2, tig = lane & 3;
    const int p = gid & 3;
    const int grb = (row0 + wm * 64) >> 2;
#pragma unroll
    for (int i = 0; i < 4; ++i) {
        int gr_lo = grb + i * 4 + (gid >> 2);
#pragma unroll
        for (int n = 0; n < 4; ++n) {
            int c = col0 + wn * 32 + n * 8 + tig * 2;
            bool cv = (c < Ncols);
            float b0 = cv ? bias[c] : 0.f,            b1 = cv ? bias[c + 1] : 0.f;
            float w0 = cv ? w2[p * Ncols + c] : 0.f,  w1 = cv ? w2[p * Ncols + c + 1] : 0.f;
            float y0 = lrelu(acc[i][n][0] + b0) * w0;
            float y1 = lrelu(acc[i][n][1] + b1) * w1;
            float y2 = lrelu(acc[i][n][2] + b0) * w0;
            float y3 = lrelu(acc[i][n][3] + b1) * w1;
            y0 += __shfl_xor_sync(0xffffffffu, y0, 4);
            y1 += __shfl_xor_sync(0xffffffffu, y1, 4);
            y2 += __shfl_xor_sync(0xffffffffu, y2, 4);
            y3 += __shfl_xor_sync(0xffffffffu, y3, 4);
            y0 += __shfl_xor_sync(0xffffffffu, y0, 8);
            y1 += __shfl_xor_sync(0xffffffffu, y1, 8);
            y2 += __shfl_xor_sync(0xffffffffu, y2, 8);
            y3 += __shfl_xor_sync(0xffffffffu, y3, 8);
            if (p == 0) {
                __nv_bfloat162 lo = __floats2bfloat162_rn(y0, y1);
                __nv_bfloat162 hi = __floats2bfloat162_rn(y2, y3);
                *(uint32_t*)(g2out + (size_t)gr_lo * g2stride + c)       = *(uint32_t*)&lo;
                *(uint32_t*)(g2out + (size_t)(gr_lo + 2) * g2stride + c) = *(uint32_t*)&hi;
            }
        }
    }
    cudaTriggerProgrammaticLaunchCompletion();
}

// ================= GEMM2: CTA 64x64, 128 threads, warp 32x32, 3-stage (proven) =================
constexpr int ST2   = 16384;
constexpr int SMEM2 = 3 * ST2;

__global__ __launch_bounds__(128, 4)
void gemm2_small(const __nv_bfloat16* __restrict__ A, const __nv_bfloat16* __restrict__ Bt,
                 const float* __restrict__ bias, float* __restrict__ C,
                 int Ncols, int lda, int ldb, int ntiles) {
    extern __shared__ char smem[];
    const uint32_t sb = smem_u32(smem);
    const int tid  = threadIdx.x;
    const int lane = tid & 31, warp = tid >> 5;
    const int wm = warp & 1, wn = warp >> 1;
    const int row0 = blockIdx.y * 64;
    const int col0 = blockIdx.x * 64;

    const int crow = tid >> 3, ccol = tid & 7;
    const char* ag0 = (const char*)(A  + (size_t)(row0 + crow) * lda) + ccol * 16;
    const char* bg0 = (const char*)(Bt + (size_t)(col0 + crow) * ldb) + ccol * 16;
    const uint32_t csw = (uint32_t)(crow * 128 + ((ccol ^ (crow & 7)) << 4));
    const uint32_t asw0 = sb + csw;
    const uint32_t bsw0 = sb + 8192u + csw;
    const size_t astep = (size_t)16 * lda * 2;
    const size_t bstep = (size_t)16 * ldb * 2;

    uint32_t a_rb[2]; int a_r7[2];
    {
        int rc = wm * 32 + (lane & 15);
#pragma unroll
        for (int i = 0; i < 2; ++i) { int r = rc + i * 16; a_rb[i] = (uint32_t)r << 7; a_r7[i] = r & 7; }
    }
    const int a_hi = lane >> 4;
    uint32_t b_rb[2]; int b_r7[2];
    {
        int rc = wn * 32 + ((lane >> 4) << 3) + (lane & 7);
#pragma unroll
        for (int g = 0; g < 2; ++g) { int r = rc + g * 16; b_rb[g] = (uint32_t)r << 7; b_r7[g] = r & 7; }
    }
    const int b_hi = (lane >> 3) & 1;

    float acc[2][4][4] = {};

    cudaGridDependencySynchronize();

#pragma unroll
    for (int s = 0; s < 2; ++s) {
        const uint32_t so = (uint32_t)s * ST2;
        const int koff = s * 128;
#pragma unroll
        for (int i = 0; i < 4; ++i) CP_ASYNC16(asw0 + so + 2048u * i, ag0 + koff + i * astep);
#pragma unroll
        for (int i = 0; i < 4; ++i) CP_ASYNC16(bsw0 + so + 2048u * i, bg0 + koff + i * bstep);
        CP_COMMIT();
    }

    int cur = 0, nxt = 2;
    for (int kt = 0; kt < ntiles; ++kt) {
        if (kt + 1 < ntiles) { CP_WAIT1(); } else { CP_WAIT0(); }
        __syncthreads();

        if (kt + 2 < ntiles) {
            const uint32_t so = (uint32_t)nxt * ST2;
            const int koff = (kt + 2) * 128;
#pragma unroll
            for (int i = 0; i < 4; ++i) CP_ASYNC16(asw0 + so + 2048u * i, ag0 + koff + i * astep);
#pragma unroll
            for (int i = 0; i < 4; ++i) CP_ASYNC16(bsw0 + so + 2048u * i, bg0 + koff + i * bstep);
            CP_COMMIT();
        }

        const uint32_t st = (uint32_t)cur * ST2;
#pragma unroll
        for (int s = 0; s < 4; ++s) {
            uint32_t af[2][4], bf[2][4];
#pragma unroll
            for (int i = 0; i < 2; ++i) {
                uint32_t addr = sb + st + a_rb[i] +
                                ((uint32_t)((2 * s + a_hi) ^ a_r7[i]) << 4);
                LDSM_X4(af[i], addr);
            }
#pragma unroll
            for (int g = 0; g < 2; ++g) {
                uint32_t addr = sb + st + 8192u + b_rb[g] +
                                ((uint32_t)((2 * s + b_hi) ^ b_r7[g]) << 4);
                LDSM_X4(bf[g], addr);
            }
#pragma unroll
            for (int i = 0; i < 2; ++i)
#pragma unroll
                for (int n = 0; n < 4; ++n)
                    MMA_BF16(acc[i][n], af[i], bf[n >> 1][(n & 1) * 2], bf[n >> 1][(n & 1) * 2 + 1]);
        }
        cur = (cur == 2) ? 0 : cur + 1;
        nxt = (nxt == 2) ? 0 : nxt + 1;
    }

    const int gid = lane >> 2, tig = lane & 3;
#pragma unroll
    for (int i = 0; i < 2; ++i) {
        int r_lo = row0 + wm * 32 + i * 16 + gid;
        int r_hi = r_lo + 8;
#pragma unroll
        for (int n = 0; n < 4; ++n) {
            int c = col0 + wn * 32 + n * 8 + tig * 2;
            if (c < Ncols) {
                float b0 = bias[c], b1 = bias[c + 1];
                float v0 = lrelu(acc[i][n][0] + b0), v1 = lrelu(acc[i][n][1] + b1);
                float v2 = lrelu(acc[i][n][2] + b0), v3 = lrelu(acc[i][n][3] + b1);
                *(float2*)(C + (size_t)r_lo * Ncols + c) = make_float2(v0, v1);
                *(float2*)(C + (size_t)r_hi * Ncols + c) = make_float2(v2, v3);
            }
        }
    }
}

// ---------------- launcher: R14 chain + PDL on the GEMM launches ----------------
static cudaStream_t g_s1 = nullptr;
static cudaEvent_t  g_evF = nullptr, g_evT = nullptr;

extern "C" void kernel_launch(void* const* d_in, const int* in_sizes, int n_in,
                              void* d_out, int out_size) {
    const float* x   = (const float*)d_in[0];
    const float* c1w = (const float*)d_in[1];   // conv1_w [4,2048]
    const float* p1W = (const float*)d_in[4];   // prop1_W [2048,1100]
    const float* p1B = (const float*)d_in[5];   // prop1_B [1100]
    const float* c2w = (const float*)d_in[6];   // conv2_w [4,1100]
    const float* p2W = (const float*)d_in[9];   // prop2_W [1100,512]
    const float* p2B = (const float*)d_in[10];  // prop2_B [512]
    float* out = (float*)d_out;                 // [2048,512]
    // d_in[2,3,7,8]: pool weights — dead code (adjacency normalizes to identity)

    __nv_bfloat16 *g1, *g2, *bt1, *bt2;
    cudaGetSymbolAddress((void**)&g1,  g_g1);
    cudaGetSymbolAddress((void**)&g2,  g_g2);
    cudaGetSymbolAddress((void**)&bt1, g_bt1);
    cudaGetSymbolAddress((void**)&bt2, g_bt2);

    if (!g_s1) {    // first call is the uncaptured correctness run: safe to create here
        cudaStreamCreateWithFlags(&g_s1, cudaStreamNonBlocking);
        cudaEventCreateWithFlags(&g_evF, cudaEventDisableTiming);
        cudaEventCreateWithFlags(&g_evT, cudaEventDisableTiming);
        cudaFuncSetAttribute(gemm1_fused, cudaFuncAttributeMaxDynamicSharedMemorySize, SMEM1);
        cudaFuncSetAttribute(gemm2_small, cudaFuncAttributeMaxDynamicSharedMemorySize, SMEM2);
    }

    // fork FROM the capture stream: side stream joins the capture via evF
    cudaEventRecord(g_evF, 0);
    cudaStreamWaitEvent(g_s1, g_evF, 0);

    // side stream (in-graph): weight transposes, parallel with conv1
    transpose_bf16<<<dim3(Fdim / 32, N1PAD / 32), dim3(32, 8), 0, g_s1>>>(
        p1W, bt1, Fdim, HID, Fdim, N1PAD);
    transpose_bf16<<<dim3(K2PAD / 32, NCLS / 32), dim3(32, 8), 0, g_s1>>>(
        p2W, bt2, HID, NCLS, K2PAD, NCLS);
    cudaEventRecord(g_evT, g_s1);

    // capture stream: conv1
    {
        long total = (long)M1 * (Fdim / 8);
        node_conv4_bf16<Fdim><<<(int)((total + 255) / 256), 256>>>(x, c1w, g1, M1);
    }
    cudaStreamWaitEvent(0, g_evT, 0);

    // GEMM1 with PDL: launches during conv tail, griddepsync gates data reads
    {
        cudaLaunchAttribute attr[1];
        attr[0].id = cudaLaunchAttributeProgrammaticStreamSerialization;
        attr[0].val.programmaticStreamSerializationAllowed = 1;
        cudaLaunchConfig_t cfg{};
        cfg.gridDim = dim3(N1PAD / 128, M1 / 128);
        cfg.blockDim = dim3(256);
        cfg.dynamicSmemBytes = SMEM1;
        cfg.stream = 0;
        cfg.attrs = attr;
        cfg.numAttrs = 1;
        cudaLaunchKernelEx(&cfg, gemm1_fused,
                           (const __nv_bfloat16*)g1, (const __nv_bfloat16*)bt1, p1B, c2w,
                           (__nv_bfloat16*)g2, HID, Fdim, Fdim, Fdim / 64, K2PAD);
    }

    // GEMM2 with PDL: launches during GEMM1 tail
    {
        cudaLaunchAttribute attr[1];
        attr[0].id = cudaLaunchAttributeProgrammaticStreamSerialization;
        attr[0].val.programmaticStreamSerializationAllowed = 1;
        cudaLaunchConfig_t cfg{};
        cfg.gridDim = dim3(NCLS / 64, M2 / 64);
        cfg.blockDim = dim3(128);
        cfg.dynamicSmemBytes = SMEM2;
        cfg.stream = 0;
        cfg.attrs = attr;
        cfg.numAttrs = 1;
        cudaLaunchKernelEx(&cfg, gemm2_small,
                           (const __nv_bfloat16*)g2, (const __nv_bfloat16*)bt2, p2B, out,
                           NCLS, K2PAD, K2PAD, K2PAD / 64);
    }
}

// round 16
// speedup vs baseline: 1.0727x; 1.0088x over previous
#include <cuda_runtime.h>
#include <cuda_bf16.h>
#include <cstdint>

// ---------------- problem constants ----------------
constexpr int Fdim = 2048;
constexpr int HID  = 1100;
constexpr int NCLS = 512;
constexpr int M1   = 8192;     // 64 * 512/4
constexpr int M2   = 2048;     // M1 / 4
constexpr int N1PAD = 1152;    // HID padded to mult of 128 (GEMM1 N)
constexpr int K2PAD = 1152;    // = N1PAD; GEMM2 K padding

// ---------------- scratch (no cudaMalloc allowed) ----------------
__device__ __align__(16) __nv_bfloat16 g_g1 [M1 * Fdim];     // conv1 out (bf16)  32 MB
__device__ __align__(16) __nv_bfloat16 g_g2 [M2 * K2PAD];    // fused conv2 out   4.7 MB
__device__ __align__(16) __nv_bfloat16 g_bt1[N1PAD * Fdim];  // prop1_W^T bf16    4.7 MB
__device__ __align__(16) __nv_bfloat16 g_bt2[NCLS * K2PAD];  // prop2_W^T bf16    1.2 MB

// ---------------- helpers ----------------
__device__ __forceinline__ uint32_t smem_u32(const void* p) {
    uint32_t a;
    asm("{ .reg .u64 t; cvta.to.shared.u64 t, %1; cvt.u32.u64 %0, t; }" : "=r"(a) : "l"(p));
    return a;
}

#define CP_ASYNC16(saddr, gptr) \
    asm volatile("cp.async.cg.shared.global [%0], [%1], 16;" :: "r"(saddr), "l"(gptr))
#define CP_COMMIT()  asm volatile("cp.async.commit_group;" ::: "memory")
#define CP_WAIT1()   asm volatile("cp.async.wait_group 1;" ::: "memory")
#define CP_WAIT0()   asm volatile("cp.async.wait_group 0;" ::: "memory")

#define LDSM_X4(r, addr) \
    asm volatile("ldmatrix.sync.aligned.m8n8.x4.shared.b16 {%0,%1,%2,%3}, [%4];" \
        : "=r"((r)[0]), "=r"((r)[1]), "=r"((r)[2]), "=r"((r)[3]) : "r"(addr))

#define MMA_BF16(c, a, b0, b1) \
    asm volatile("mma.sync.aligned.m16n8k16.row.col.f32.bf16.bf16.f32 " \
        "{%0,%1,%2,%3}, {%4,%5,%6,%7}, {%8,%9}, {%0,%1,%2,%3};" \
        : "+f"((c)[0]), "+f"((c)[1]), "+f"((c)[2]), "+f"((c)[3]) \
        : "r"((a)[0]), "r"((a)[1]), "r"((a)[2]), "r"((a)[3]), "r"(b0), "r"(b1))

__device__ __forceinline__ float lrelu(float v) { return (v >= 0.f) ? v : 0.01f * v; }

// ---------------- node conv: coalesced panels + streaming cache hints ----------------
// x is a 256MB single-use stream: __ldcs (evict-first). w is tiny + reused: __ldg.
// g1 stores: __stcs (streaming; consumed once by GEMM1 much later).
template<int FD>
__global__ void node_conv4_bf16(const float* __restrict__ x, const float* __restrict__ w,
                                __nv_bfloat16* __restrict__ out, int rows) {
    constexpr int F4 = FD / 4;      // float4 per row
    constexpr int F8 = F4 / 2;      // panel width in float4
    long idx = (long)blockIdx.x * blockDim.x + threadIdx.x;
    if (idx < (long)rows * F8) {
        int r = (int)(idx / F8);
        int j = (int)(idx % F8);
        const float4* x4 = (const float4*)x;
        const float4* w4 = (const float4*)w;
        float4 a0 = make_float4(0.f, 0.f, 0.f, 0.f);
        float4 a1 = make_float4(0.f, 0.f, 0.f, 0.f);
#pragma unroll
        for (int p = 0; p < 4; ++p) {
            const float4* xr = x4 + (long)(4 * r + p) * F4;
            const float4* wr = w4 + p * F4;
            float4 xv0 = __ldcs(xr + j),      wv0 = __ldg(wr + j);
            float4 xv1 = __ldcs(xr + j + F8), wv1 = __ldg(wr + j + F8);
            a0.x = fmaf(xv0.x, wv0.x, a0.x); a0.y = fmaf(xv0.y, wv0.y, a0.y);
            a0.z = fmaf(xv0.z, wv0.z, a0.z); a0.w = fmaf(xv0.w, wv0.w, a0.w);
            a1.x = fmaf(xv1.x, wv1.x, a1.x); a1.y = fmaf(xv1.y, wv1.y, a1.y);
            a1.z = fmaf(xv1.z, wv1.z, a1.z); a1.w = fmaf(xv1.w, wv1.w, a1.w);
        }
        __nv_bfloat162 b0 = __floats2bfloat162_rn(a0.x, a0.y);
        __nv_bfloat162 b1 = __floats2bfloat162_rn(a0.z, a0.w);
        __nv_bfloat162 b2 = __floats2bfloat162_rn(a1.x, a1.y);
        __nv_bfloat162 b3 = __floats2bfloat162_rn(a1.z, a1.w);
        uint2 v0, v1;
        v0.x = *(uint32_t*)&b0; v0.y = *(uint32_t*)&b1;
        v1.x = *(uint32_t*)&b2; v1.y = *(uint32_t*)&b3;
        uint2* o2 = (uint2*)out + (long)r * F4;
        __stcs(o2 + j,      v0);
        __stcs(o2 + j + F8, v1);
    }
    cudaTriggerProgrammaticLaunchCompletion();
}

// ---------------- transpose + bf16 round + zero pad:  W[K][N] -> Bt[Npad][Kpad] ----------------
__global__ void transpose_bf16(const float* __restrict__ W, __nv_bfloat16* __restrict__ Bt,
                               int K, int N, int Kpad, int Npad) {
    __shared__ float t[32][33];
    int k0 = blockIdx.x * 32, n0 = blockIdx.y * 32;
#pragma unroll
    for (int i = 0; i < 4; ++i) {
        int k = k0 + threadIdx.y + i * 8;
        int n = n0 + threadIdx.x;
        t[threadIdx.y + i * 8][threadIdx.x] = (k < K && n < N) ? W[(long)k * N + n] : 0.f;
    }
    __syncthreads();
#pragma unroll
    for (int i = 0; i < 4; ++i) {
        int n = n0 + threadIdx.y + i * 8;
        int k = k0 + threadIdx.x;
        if (n < Npad && k < Kpad)
            Bt[(long)n * Kpad + k] = __float2bfloat16_rn(t[threadIdx.x][threadIdx.y + i * 8]);
    }
}

// ================= GEMM1 (fused conv2): CTA 128x128, 256 thr, warp 64x32, 3-stage (proven) =================
constexpr int ST1   = 32768;               // A 16KB + B 16KB
constexpr int SMEM1 = 3 * ST1;             // 98304 B

__global__ __launch_bounds__(256, 2)
void gemm1_fused(const __nv_bfloat16* __restrict__ A, const __nv_bfloat16* __restrict__ Bt,
                 const float* __restrict__ bias, const float* __restrict__ w2,
                 __nv_bfloat16* __restrict__ g2out,
                 int Ncols, int lda, int ldb, int ntiles, int g2stride) {
    extern __shared__ char smem[];
    const uint32_t sb = smem_u32(smem);
    const int tid  = threadIdx.x;
    const int lane = tid & 31, warp = tid >> 5;
    const int wm = warp & 1, wn = warp >> 1;
    const int row0 = blockIdx.y * 128;
    const int col0 = blockIdx.x * 128;

    const char* ag[4]; uint32_t asw[4];
    const char* bg[4]; uint32_t bsw[4];
#pragma unroll
    for (int i = 0; i < 4; ++i) {
        int idx = i * 256 + tid;
        int row = idx >> 3, col = idx & 7;
        ag[i]  = (const char*)(A + (size_t)(row0 + row) * lda) + col * 16;
        asw[i] = sb + (uint32_t)(row * 128 + ((col ^ (row & 7)) << 4));
        bg[i]  = (const char*)(Bt + (size_t)(col0 + row) * ldb) + col * 16;
        bsw[i] = sb + 16384u + (uint32_t)(row * 128 + ((col ^ (row & 7)) << 4));
    }

    uint32_t a_rb[4]; int a_r7[4];
    {
        int rc = wm * 64 + (lane & 15);
#pragma unroll
        for (int i = 0; i < 4; ++i) { int r = rc + i * 16; a_rb[i] = (uint32_t)r << 7; a_r7[i] = r & 7; }
    }
    const int a_hi = lane >> 4;
    uint32_t b_rb[2]; int b_r7[2];
    {
        int rc = wn * 32 + ((lane >> 4) << 3) + (lane & 7);
#pragma unroll
        for (int g = 0; g < 2; ++g) { int r = rc + g * 16; b_rb[g] = (uint32_t)r << 7; b_r7[g] = r & 7; }
    }
    const int b_hi = (lane >> 3) & 1;

    float acc[4][4][4] = {};

    // PDL: launched during producer tail; block here until producer data is visible
    cudaGridDependencySynchronize();

#pragma unroll
    for (int s = 0; s < 2; ++s) {
        const uint32_t so = (uint32_t)s * ST1;
        const int koff = s * 128;
#pragma unroll
        for (int i = 0; i < 4; ++i) CP_ASYNC16(asw[i] + so, ag[i] + koff);
#pragma unroll
        for (int i = 0; i < 4; ++i) CP_ASYNC16(bsw[i] + so, bg[i] + koff);
        CP_COMMIT();
    }

    int cur = 0, nxt = 2;
    for (int kt = 0; kt < ntiles; ++kt) {
        if (kt + 1 < ntiles) { CP_WAIT1(); } else { CP_WAIT0(); }
        __syncthreads();

        if (kt + 2 < ntiles) {
            const uint32_t so = (uint32_t)nxt * ST1;
            const int koff = (kt + 2) * 128;
#pragma unroll
            for (int i = 0; i < 4; ++i) CP_ASYNC16(asw[i] + so, ag[i] + koff);
#pragma unroll
            for (int i = 0; i < 4; ++i) CP_ASYNC16(bsw[i] + so, bg[i] + koff);
            CP_COMMIT();
        }

        const uint32_t st = (uint32_t)cur * ST1;
#pragma unroll
        for (int s = 0; s < 4; ++s) {
            uint32_t af[4][4], bf[2][4];
#pragma unroll
            for (int i = 0; i < 4; ++i) {
                uint32_t addr = sb + st + a_rb[i] +
                                ((uint32_t)((2 * s + a_hi) ^ a_r7[i]) << 4);
                LDSM_X4(af[i], addr);
            }
#pragma unroll
            for (int g = 0; g < 2; ++g) {
                uint32_t addr = sb + st + 16384u + b_rb[g] +
                                ((uint32_t)((2 * s + b_hi) ^ b_r7[g]) << 4);
                LDSM_X4(bf[g], addr);
            }
#pragma unroll
            for (int i = 0; i < 4; ++i)
#pragma unroll
                for (int n = 0; n < 4; ++n)
                    MMA_BF16(acc[i][n], af[i], bf[n >> 1][(n & 1) * 2], bf[n >> 1][(n & 1) * 2 + 1]);
        }
        cur = (cur == 2) ? 0 : cur + 1;
        nxt = (nxt == 2) ? 0 : nxt + 1;
    }

    // ---- fused epilogue: leaky + conv2 reduce over p = row&3 (shfl.bfly) ----
    const int gid = lane >> 2, tig = lane & 3;
    const int p = gid & 3;
    const int grb = (row0 + wm * 64) >> 2;
#pragma unroll
    for (int i = 0; i < 4; ++i) {
        int gr_lo = grb + i * 4 + (gid >> 2);
#pragma unroll
        for (int n = 0; n < 4; ++n) {
            int c = col0 + wn * 32 + n * 8 + tig * 2;
            bool cv = (c < Ncols);
            float b0 = cv ? bias[c] : 0.f,            b1 = cv ? bias[c + 1] : 0.f;
            float w0 = cv ? w2[p * Ncols + c] : 0.f,  w1 = cv ? w2[p * Ncols + c + 1] : 0.f;
            float y0 = lrelu(acc[i][n][0] + b0) * w0;
            float y1 = lrelu(acc[i][n][1] + b1) * w1;
            float y2 = lrelu(acc[i][n][2] + b0) * w0;
            float y3 = lrelu(acc[i][n][3] + b1) * w1;
            y0 += __shfl_xor_sync(0xffffffffu, y0, 4);
            y1 += __shfl_xor_sync(0xffffffffu, y1, 4);
            y2 += __shfl_xor_sync(0xffffffffu, y2, 4);
            y3 += __shfl_xor_sync(0xffffffffu, y3, 4);
            y0 += __shfl_xor_sync(0xffffffffu, y0, 8);
            y1 += __shfl_xor_sync(0xffffffffu, y1, 8);
            y2 += __shfl_xor_sync(0xffffffffu, y2, 8);
            y3 += __shfl_xor_sync(0xffffffffu, y3, 8);
            if (p == 0) {
                __nv_bfloat162 lo = __floats2bfloat162_rn(y0, y1);
                __nv_bfloat162 hi = __floats2bfloat162_rn(y2, y3);
                *(uint32_t*)(g2out + (size_t)gr_lo * g2stride + c)       = *(uint32_t*)&lo;
                *(uint32_t*)(g2out + (size_t)(gr_lo + 2) * g2stride + c) = *(uint32_t*)&hi;
            }
        }
    }
    cudaTriggerProgrammaticLaunchCompletion();
}

// ================= GEMM2: CTA 64x64, 128 threads, warp 32x32, 3-stage (proven) =================
constexpr int ST2   = 16384;
constexpr int SMEM2 = 3 * ST2;

__global__ __launch_bounds__(128, 4)
void gemm2_small(const __nv_bfloat16* __restrict__ A, const __nv_bfloat16* __restrict__ Bt,
                 const float* __restrict__ bias, float* __restrict__ C,
                 int Ncols, int lda, int ldb, int ntiles) {
    extern __shared__ char smem[];
    const uint32_t sb = smem_u32(smem);
    const int tid  = threadIdx.x;
    const int lane = tid & 31, warp = tid >> 5;
    const int wm = warp & 1, wn = warp >> 1;
    const int row0 = blockIdx.y * 64;
    const int col0 = blockIdx.x * 64;

    const int crow = tid >> 3, ccol = tid & 7;
    const char* ag0 = (const char*)(A  + (size_t)(row0 + crow) * lda) + ccol * 16;
    const char* bg0 = (const char*)(Bt + (size_t)(col0 + crow) * ldb) + ccol * 16;
    const uint32_t csw = (uint32_t)(crow * 128 + ((ccol ^ (crow & 7)) << 4));
    const uint32_t asw0 = sb + csw;
    const uint32_t bsw0 = sb + 8192u + csw;
    const size_t astep = (size_t)16 * lda * 2;
    const size_t bstep = (size_t)16 * ldb * 2;

    uint32_t a_rb[2]; int a_r7[2];
    {
        int rc = wm * 32 + (lane & 15);
#pragma unroll
        for (int i = 0; i < 2; ++i) { int r = rc + i * 16; a_rb[i] = (uint32_t)r << 7; a_r7[i] = r & 7; }
    }
    const int a_hi = lane >> 4;
    uint32_t b_rb[2]; int b_r7[2];
    {
        int rc = wn * 32 + ((lane >> 4) << 3) + (lane & 7);
#pragma unroll
        for (int g = 0; g < 2; ++g) { int r = rc + g * 16; b_rb[g] = (uint32_t)r << 7; b_r7[g] = r & 7; }
    }
    const int b_hi = (lane >> 3) & 1;

    float acc[2][4][4] = {};

    cudaGridDependencySynchronize();

#pragma unroll
    for (int s = 0; s < 2; ++s) {
        const uint32_t so = (uint32_t)s * ST2;
        const int koff = s * 128;
#pragma unroll
        for (int i = 0; i < 4; ++i) CP_ASYNC16(asw0 + so + 2048u * i, ag0 + koff + i * astep);
#pragma unroll
        for (int i = 0; i < 4; ++i) CP_ASYNC16(bsw0 + so + 2048u * i, bg0 + koff + i * bstep);
        CP_COMMIT();
    }

    int cur = 0, nxt = 2;
    for (int kt = 0; kt < ntiles; ++kt) {
        if (kt + 1 < ntiles) { CP_WAIT1(); } else { CP_WAIT0(); }
        __syncthreads();

        if (kt + 2 < ntiles) {
            const uint32_t so = (uint32_t)nxt * ST2;
            const int koff = (kt + 2) * 128;
#pragma unroll
            for (int i = 0; i < 4; ++i) CP_ASYNC16(asw0 + so + 2048u * i, ag0 + koff + i * astep);
#pragma unroll
            for (int i = 0; i < 4; ++i) CP_ASYNC16(bsw0 + so + 2048u * i, bg0 + koff + i * bstep);
            CP_COMMIT();
        }

        const uint32_t st = (uint32_t)cur * ST2;
#pragma unroll
        for (int s = 0; s < 4; ++s) {
            uint32_t af[2][4], bf[2][4];
#pragma unroll
            for (int i = 0; i < 2; ++i) {
                uint32_t addr = sb + st + a_rb[i] +
                                ((uint32_t)((2 * s + a_hi) ^ a_r7[i]) << 4);
                LDSM_X4(af[i], addr);
            }
#pragma unroll
            for (int g = 0; g < 2; ++g) {
                uint32_t addr = sb + st + 8192u + b_rb[g] +
                                ((uint32_t)((2 * s + b_hi) ^ b_r7[g]) << 4);
                LDSM_X4(bf[g], addr);
            }
#pragma unroll
            for (int i = 0; i < 2; ++i)
#pragma unroll
                for (int n = 0; n < 4; ++n)
                    MMA_BF16(acc[i][n], af[i], bf[n >> 1][(n & 1) * 2], bf[n >> 1][(n & 1) * 2 + 1]);
        }
        cur = (cur == 2) ? 0 : cur + 1;
        nxt = (nxt == 2) ? 0 : nxt + 1;
    }

    const int gid = lane >> 2, tig = lane & 3;
#pragma unroll
    for (int i = 0; i < 2; ++i) {
        int r_lo = row0 + wm * 32 + i * 16 + gid;
        int r_hi = r_lo + 8;
#pragma unroll
        for (int n = 0; n < 4; ++n) {
            int c = col0 + wn * 32 + n * 8 + tig * 2;
            if (c < Ncols) {
                float b0 = bias[c], b1 = bias[c + 1];
                float v0 = lrelu(acc[i][n][0] + b0), v1 = lrelu(acc[i][n][1] + b1);
                float v2 = lrelu(acc[i][n][2] + b0), v3 = lrelu(acc[i][n][3] + b1);
                *(float2*)(C + (size_t)r_lo * Ncols + c) = make_float2(v0, v1);
                *(float2*)(C + (size_t)r_hi * Ncols + c) = make_float2(v2, v3);
            }
        }
    }
}

// ---------------- launcher: R15 chain (fork/join transposes + PDL GEMMs) ----------------
static cudaStream_t g_s1 = nullptr;
static cudaEvent_t  g_evF = nullptr, g_evT = nullptr;

extern "C" void kernel_launch(void* const* d_in, const int* in_sizes, int n_in,
                              void* d_out, int out_size) {
    const float* x   = (const float*)d_in[0];
    const float* c1w = (const float*)d_in[1];   // conv1_w [4,2048]
    const float* p1W = (const float*)d_in[4];   // prop1_W [2048,1100]
    const float* p1B = (const float*)d_in[5];   // prop1_B [1100]
    const float* c2w = (const float*)d_in[6];   // conv2_w [4,1100]
    const float* p2W = (const float*)d_in[9];   // prop2_W [1100,512]
    const float* p2B = (const float*)d_in[10];  // prop2_B [512]
    float* out = (float*)d_out;                 // [2048,512]
    // d_in[2,3,7,8]: pool weights — dead code (adjacency normalizes to identity)

    __nv_bfloat16 *g1, *g2, *bt1, *bt2;
    cudaGetSymbolAddress((void**)&g1,  g_g1);
    cudaGetSymbolAddress((void**)&g2,  g_g2);
    cudaGetSymbolAddress((void**)&bt1, g_bt1);
    cudaGetSymbolAddress((void**)&bt2, g_bt2);

    if (!g_s1) {    // first call is the uncaptured correctness run: safe to create here
        cudaStreamCreateWithFlags(&g_s1, cudaStreamNonBlocking);
        cudaEventCreateWithFlags(&g_evF, cudaEventDisableTiming);
        cudaEventCreateWithFlags(&g_evT, cudaEventDisableTiming);
        cudaFuncSetAttribute(gemm1_fused, cudaFuncAttributeMaxDynamicSharedMemorySize, SMEM1);
        cudaFuncSetAttribute(gemm2_small, cudaFuncAttributeMaxDynamicSharedMemorySize, SMEM2);
    }

    // fork FROM the capture stream: side stream joins the capture via evF
    cudaEventRecord(g_evF, 0);
    cudaStreamWaitEvent(g_s1, g_evF, 0);

    // side stream (in-graph): weight transposes, parallel with conv1
    transpose_bf16<<<dim3(Fdim / 32, N1PAD / 32), dim3(32, 8), 0, g_s1>>>(
        p1W, bt1, Fdim, HID, Fdim, N1PAD);
    transpose_bf16<<<dim3(K2PAD / 32, NCLS / 32), dim3(32, 8), 0, g_s1>>>(
        p2W, bt2, HID, NCLS, K2PAD, NCLS);
    cudaEventRecord(g_evT, g_s1);

    // capture stream: conv1
    {
        long total = (long)M1 * (Fdim / 8);
        node_conv4_bf16<Fdim><<<(int)((total + 255) / 256), 256>>>(x, c1w, g1, M1);
    }
    cudaStreamWaitEvent(0, g_evT, 0);

    // GEMM1 with PDL: launches during conv tail, griddepsync gates data reads
    {
        cudaLaunchAttribute attr[1];
        attr[0].id = cudaLaunchAttributeProgrammaticStreamSerialization;
        attr[0].val.programmaticStreamSerializationAllowed = 1;
        cudaLaunchConfig_t cfg{};
        cfg.gridDim = dim3(N1PAD / 128, M1 / 128);
        cfg.blockDim = dim3(256);
        cfg.dynamicSmemBytes = SMEM1;
        cfg.stream = 0;
        cfg.attrs = attr;
        cfg.numAttrs = 1;
        cudaLaunchKernelEx(&cfg, gemm1_fused,
                           (const __nv_bfloat16*)g1, (const __nv_bfloat16*)bt1, p1B, c2w,
                           (__nv_bfloat16*)g2, HID, Fdim, Fdim, Fdim / 64, K2PAD);
    }

    // GEMM2 with PDL: launches during GEMM1 tail
    {
        cudaLaunchAttribute attr[1];
        attr[0].id = cudaLaunchAttributeProgrammaticStreamSerialization;
        attr[0].val.programmaticStreamSerializationAllowed = 1;
        cudaLaunchConfig_t cfg{};
        cfg.gridDim = dim3(NCLS / 64, M2 / 64);
        cfg.blockDim = dim3(128);
        cfg.dynamicSmemBytes = SMEM2;
        cfg.stream = 0;
        cfg.attrs = attr;
        cfg.numAttrs = 1;
        cudaLaunchKernelEx(&cfg, gemm2_small,
                           (const __nv_bfloat16*)g2, (const __nv_bfloat16*)bt2, p2B, out,
                           NCLS, K2PAD, K2PAD, K2PAD / 64);
    }
}

// round 17
// speedup vs baseline: 1.0856x; 1.0121x over previous
#include <cuda_runtime.h>
#include <cuda_bf16.h>
#include <cstdint>

// ---------------- problem constants ----------------
constexpr int Fdim = 2048;
constexpr int HID  = 1100;
constexpr int NCLS = 512;
constexpr int M1   = 8192;     // 64 * 512/4
constexpr int M2   = 2048;     // M1 / 4
constexpr int N1PAD = 1152;    // HID padded to mult of 128 (GEMM1 N)
constexpr int K2PAD = 1152;    // = N1PAD; GEMM2 K padding

// ---------------- scratch (no cudaMalloc allowed) ----------------
__device__ __align__(16) __nv_bfloat16 g_g1 [M1 * Fdim];     // conv1 out (bf16)  32 MB
__device__ __align__(16) __nv_bfloat16 g_g2 [M2 * K2PAD];    // fused conv2 out   4.7 MB
__device__ __align__(16) __nv_bfloat16 g_bt1[N1PAD * Fdim];  // prop1_W^T bf16    4.7 MB
__device__ __align__(16) __nv_bfloat16 g_bt2[NCLS * K2PAD];  // prop2_W^T bf16    1.2 MB

// ---------------- helpers ----------------
__device__ __forceinline__ uint32_t smem_u32(const void* p) {
    uint32_t a;
    asm("{ .reg .u64 t; cvta.to.shared.u64 t, %1; cvt.u32.u64 %0, t; }" : "=r"(a) : "l"(p));
    return a;
}

#define CP_ASYNC16(saddr, gptr) \
    asm volatile("cp.async.cg.shared.global [%0], [%1], 16;" :: "r"(saddr), "l"(gptr))
#define CP_COMMIT()  asm volatile("cp.async.commit_group;" ::: "memory")
#define CP_WAIT1()   asm volatile("cp.async.wait_group 1;" ::: "memory")
#define CP_WAIT0()   asm volatile("cp.async.wait_group 0;" ::: "memory")

#define LDSM_X4(r, addr) \
    asm volatile("ldmatrix.sync.aligned.m8n8.x4.shared.b16 {%0,%1,%2,%3}, [%4];" \
        : "=r"((r)[0]), "=r"((r)[1]), "=r"((r)[2]), "=r"((r)[3]) : "r"(addr))

#define MMA_BF16(c, a, b0, b1) \
    asm volatile("mma.sync.aligned.m16n8k16.row.col.f32.bf16.bf16.f32 " \
        "{%0,%1,%2,%3}, {%4,%5,%6,%7}, {%8,%9}, {%0,%1,%2,%3};" \
        : "+f"((c)[0]), "+f"((c)[1]), "+f"((c)[2]), "+f"((c)[3]) \
        : "r"((a)[0]), "r"((a)[1]), "r"((a)[2]), "r"((a)[3]), "r"(b0), "r"(b1))

__device__ __forceinline__ float lrelu(float v) { return (v >= 0.f) ? v : 0.01f * v; }

// ---------------- node conv: 4 coalesced panels (16 cols) per thread, streaming hints ----------------
// 16 independent __ldcs loads in flight per thread -> higher MLP toward the DRAM ceiling.
template<int FD>
__global__ void node_conv4_bf16(const float* __restrict__ x, const float* __restrict__ w,
                                __nv_bfloat16* __restrict__ out, int rows) {
    constexpr int F4  = FD / 4;     // float4 per row
    constexpr int F16 = F4 / 4;     // panel width in float4 (4 panels)
    long idx = (long)blockIdx.x * blockDim.x + threadIdx.x;
    if (idx < (long)rows * F16) {
        int r = (int)(idx / F16);
        int j = (int)(idx % F16);
        const float4* x4 = (const float4*)x;
        const float4* w4 = (const float4*)w;
        float4 acc[4] = {make_float4(0.f, 0.f, 0.f, 0.f), make_float4(0.f, 0.f, 0.f, 0.f),
                         make_float4(0.f, 0.f, 0.f, 0.f), make_float4(0.f, 0.f, 0.f, 0.f)};
#pragma unroll
        for (int p = 0; p < 4; ++p) {
            const float4* xr = x4 + (long)(4 * r + p) * F4;
            const float4* wr = w4 + p * F4;
#pragma unroll
            for (int q = 0; q < 4; ++q) {
                float4 xv = __ldcs(xr + j + q * F16);
                float4 wv = __ldg(wr + j + q * F16);
                acc[q].x = fmaf(xv.x, wv.x, acc[q].x);
                acc[q].y = fmaf(xv.y, wv.y, acc[q].y);
                acc[q].z = fmaf(xv.z, wv.z, acc[q].z);
                acc[q].w = fmaf(xv.w, wv.w, acc[q].w);
            }
        }
        uint2* o2 = (uint2*)out + (long)r * F4;
#pragma unroll
        for (int q = 0; q < 4; ++q) {
            __nv_bfloat162 lo = __floats2bfloat162_rn(acc[q].x, acc[q].y);
            __nv_bfloat162 hi = __floats2bfloat162_rn(acc[q].z, acc[q].w);
            uint2 v;
            v.x = *(uint32_t*)&lo;
            v.y = *(uint32_t*)&hi;
            __stcs(o2 + j + q * F16, v);
        }
    }
    cudaTriggerProgrammaticLaunchCompletion();
}

// ---------------- transpose + bf16 round + zero pad:  W[K][N] -> Bt[Npad][Kpad] ----------------
__global__ void transpose_bf16(const float* __restrict__ W, __nv_bfloat16* __restrict__ Bt,
                               int K, int N, int Kpad, int Npad) {
    __shared__ float t[32][33];
    int k0 = blockIdx.x * 32, n0 = blockIdx.y * 32;
#pragma unroll
    for (int i = 0; i < 4; ++i) {
        int k = k0 + threadIdx.y + i * 8;
        int n = n0 + threadIdx.x;
        t[threadIdx.y + i * 8][threadIdx.x] = (k < K && n < N) ? W[(long)k * N + n] : 0.f;
    }
    __syncthreads();
#pragma unroll
    for (int i = 0; i < 4; ++i) {
        int n = n0 + threadIdx.y + i * 8;
        int k = k0 + threadIdx.x;
        if (n < Npad && k < Kpad)
            Bt[(long)n * Kpad + k] = __float2bfloat16_rn(t[threadIdx.x][threadIdx.y + i * 8]);
    }
}

// ================= GEMM1 (fused conv2): CTA 128x128, 256 thr, warp 64x32, 3-stage (proven) =================
constexpr int ST1   = 32768;               // A 16KB + B 16KB
constexpr int SMEM1 = 3 * ST1;             // 98304 B

__global__ __launch_bounds__(256, 2)
void gemm1_fused(const __nv_bfloat16* __restrict__ A, const __nv_bfloat16* __restrict__ Bt,
                 const float* __restrict__ bias, const float* __restrict__ w2,
                 __nv_bfloat16* __restrict__ g2out,
                 int Ncols, int lda, int ldb, int ntiles, int g2stride) {
    extern __shared__ char smem[];
    const uint32_t sb = smem_u32(smem);
    const int tid  = threadIdx.x;
    const int lane = tid & 31, warp = tid >> 5;
    const int wm = warp & 1, wn = warp >> 1;
    const int row0 = blockIdx.y * 128;
    const int col0 = blockIdx.x * 128;

    const char* ag[4]; uint32_t asw[4];
    const char* bg[4]; uint32_t bsw[4];
#pragma unroll
    for (int i = 0; i < 4; ++i) {
        int idx = i * 256 + tid;
        int row = idx >> 3, col = idx & 7;
        ag[i]  = (const char*)(A + (size_t)(row0 + row) * lda) + col * 16;
        asw[i] = sb + (uint32_t)(row * 128 + ((col ^ (row & 7)) << 4));
        bg[i]  = (const char*)(Bt + (size_t)(col0 + row) * ldb) + col * 16;
        bsw[i] = sb + 16384u + (uint32_t)(row * 128 + ((col ^ (row & 7)) << 4));
    }

    uint32_t a_rb[4]; int a_r7[4];
    {
        int rc = wm * 64 + (lane & 15);
#pragma unroll
        for (int i = 0; i < 4; ++i) { int r = rc + i * 16; a_rb[i] = (uint32_t)r << 7; a_r7[i] = r & 7; }
    }
    const int a_hi = lane >> 4;
    uint32_t b_rb[2]; int b_r7[2];
    {
        int rc = wn * 32 + ((lane >> 4) << 3) + (lane & 7);
#pragma unroll
        for (int g = 0; g < 2; ++g) { int r = rc + g * 16; b_rb[g] = (uint32_t)r << 7; b_r7[g] = r & 7; }
    }
    const int b_hi = (lane >> 3) & 1;

    float acc[4][4][4] = {};

    // PDL: launched during producer tail; block here until producer data is visible
    cudaGridDependencySynchronize();

#pragma unroll
    for (int s = 0; s < 2; ++s) {
        const uint32_t so = (uint32_t)s * ST1;
        const int koff = s * 128;
#pragma unroll
        for (int i = 0; i < 4; ++i) CP_ASYNC16(asw[i] + so, ag[i] + koff);
#pragma unroll
        for (int i = 0; i < 4; ++i) CP_ASYNC16(bsw[i] + so, bg[i] + koff);
        CP_COMMIT();
    }

    int cur = 0, nxt = 2;
    for (int kt = 0; kt < ntiles; ++kt) {
        if (kt + 1 < ntiles) { CP_WAIT1(); } else { CP_WAIT0(); }
        __syncthreads();

        if (kt + 2 < ntiles) {
            const uint32_t so = (uint32_t)nxt * ST1;
            const int koff = (kt + 2) * 128;
#pragma unroll
            for (int i = 0; i < 4; ++i) CP_ASYNC16(asw[i] + so, ag[i] + koff);
#pragma unroll
            for (int i = 0; i < 4; ++i) CP_ASYNC16(bsw[i] + so, bg[i] + koff);
            CP_COMMIT();
        }

        const uint32_t st = (uint32_t)cur * ST1;
#pragma unroll
        for (int s = 0; s < 4; ++s) {
            uint32_t af[4][4], bf[2][4];
#pragma unroll
            for (int i = 0; i < 4; ++i) {
                uint32_t addr = sb + st + a_rb[i] +
                                ((uint32_t)((2 * s + a_hi) ^ a_r7[i]) << 4);
                LDSM_X4(af[i], addr);
            }
#pragma unroll
            for (int g = 0; g < 2; ++g) {
                uint32_t addr = sb + st + 16384u + b_rb[g] +
                                ((uint32_t)((2 * s + b_hi) ^ b_r7[g]) << 4);
                LDSM_X4(bf[g], addr);
            }
#pragma unroll
            for (int i = 0; i < 4; ++i)
#pragma unroll
                for (int n = 0; n < 4; ++n)
                    MMA_BF16(acc[i][n], af[i], bf[n >> 1][(n & 1) * 2], bf[n >> 1][(n & 1) * 2 + 1]);
        }
        cur = (cur == 2) ? 0 : cur + 1;
        nxt = (nxt == 2) ? 0 : nxt + 1;
    }

    // ---- fused epilogue: leaky + conv2 reduce over p = row&3 (shfl.bfly) ----
    const int gid = lane >> 2, tig = lane & 3;
    const int p = gid & 3;
    const int grb = (row0 + wm * 64) >> 2;
#pragma unroll
    for (int i = 0; i < 4; ++i) {
        int gr_lo = grb + i * 4 + (gid >> 2);
#pragma unroll
        for (int n = 0; n < 4; ++n) {
            int c = col0 + wn * 32 + n * 8 + tig * 2;
            bool cv = (c < Ncols);
            float b0 = cv ? bias[c] : 0.f,            b1 = cv ? bias[c + 1] : 0.f;
            float w0 = cv ? w2[p * Ncols + c] : 0.f,  w1 = cv ? w2[p * Ncols + c + 1] : 0.f;
            float y0 = lrelu(acc[i][n][0] + b0) * w0;
            float y1 = lrelu(acc[i][n][1] + b1) * w1;
            float y2 = lrelu(acc[i][n][2] + b0) * w0;
            float y3 = lrelu(acc[i][n][3] + b1) * w1;
            y0 += __shfl_xor_sync(0xffffffffu, y0, 4);
            y1 += __shfl_xor_sync(0xffffffffu, y1, 4);
            y2 += __shfl_xor_sync(0xffffffffu, y2, 4);
            y3 += __shfl_xor_sync(0xffffffffu, y3, 4);
            y0 += __shfl_xor_sync(0xffffffffu, y0, 8);
            y1 += __shfl_xor_sync(0xffffffffu, y1, 8);
            y2 += __shfl_xor_sync(0xffffffffu, y2, 8);
            y3 += __shfl_xor_sync(0xffffffffu, y3, 8);
            if (p == 0) {
                __nv_bfloat162 lo = __floats2bfloat162_rn(y0, y1);
                __nv_bfloat162 hi = __floats2bfloat162_rn(y2, y3);
                *(uint32_t*)(g2out + (size_t)gr_lo * g2stride + c)       = *(uint32_t*)&lo;
                *(uint32_t*)(g2out + (size_t)(gr_lo + 2) * g2stride + c) = *(uint32_t*)&hi;
            }
        }
    }
    cudaTriggerProgrammaticLaunchCompletion();
}

// ================= GEMM2: CTA 64x64, 128 threads, warp 32x32, 3-stage (proven) =================
constexpr int ST2   = 16384;
constexpr int SMEM2 = 3 * ST2;

__global__ __launch_bounds__(128, 4)
void gemm2_small(const __nv_bfloat16* __restrict__ A, const __nv_bfloat16* __restrict__ Bt,
                 const float* __restrict__ bias, float* __restrict__ C,
                 int Ncols, int lda, int ldb, int ntiles) {
    extern __shared__ char smem[];
    const uint32_t sb = smem_u32(smem);
    const int tid  = threadIdx.x;
    const int lane = tid & 31, warp = tid >> 5;
    const int wm = warp & 1, wn = warp >> 1;
    const int row0 = blockIdx.y * 64;
    const int col0 = blockIdx.x * 64;

    const int crow = tid >> 3, ccol = tid & 7;
    const char* ag0 = (const char*)(A  + (size_t)(row0 + crow) * lda) + ccol * 16;
    const char* bg0 = (const char*)(Bt + (size_t)(col0 + crow) * ldb) + ccol * 16;
    const uint32_t csw = (uint32_t)(crow * 128 + ((ccol ^ (crow & 7)) << 4));
    const uint32_t asw0 = sb + csw;
    const uint32_t bsw0 = sb + 8192u + csw;
    const size_t astep = (size_t)16 * lda * 2;
    const size_t bstep = (size_t)16 * ldb * 2;

    uint32_t a_rb[2]; int a_r7[2];
    {
        int rc = wm * 32 + (lane & 15);
#pragma unroll
        for (int i = 0; i < 2; ++i) { int r = rc + i * 16; a_rb[i] = (uint32_t)r << 7; a_r7[i] = r & 7; }
    }
    const int a_hi = lane >> 4;
    uint32_t b_rb[2]; int b_r7[2];
    {
        int rc = wn * 32 + ((lane >> 4) << 3) + (lane & 7);
#pragma unroll
        for (int g = 0; g < 2; ++g) { int r = rc + g * 16; b_rb[g] = (uint32_t)r << 7; b_r7[g] = r & 7; }
    }
    const int b_hi = (lane >> 3) & 1;

    float acc[2][4][4] = {};

    cudaGridDependencySynchronize();

#pragma unroll
    for (int s = 0; s < 2; ++s) {
        const uint32_t so = (uint32_t)s * ST2;
        const int koff = s * 128;
#pragma unroll
        for (int i = 0; i < 4; ++i) CP_ASYNC16(asw0 + so + 2048u * i, ag0 + koff + i * astep);
#pragma unroll
        for (int i = 0; i < 4; ++i) CP_ASYNC16(bsw0 + so + 2048u * i, bg0 + koff + i * bstep);
        CP_COMMIT();
    }

    int cur = 0, nxt = 2;
    for (int kt = 0; kt < ntiles; ++kt) {
        if (kt + 1 < ntiles) { CP_WAIT1(); } else { CP_WAIT0(); }
        __syncthreads();

        if (kt + 2 < ntiles) {
            const uint32_t so = (uint32_t)nxt * ST2;
            const int koff = (kt + 2) * 128;
#pragma unroll
            for (int i = 0; i < 4; ++i) CP_ASYNC16(asw0 + so + 2048u * i, ag0 + koff + i * astep);
#pragma unroll
            for (int i = 0; i < 4; ++i) CP_ASYNC16(bsw0 + so + 2048u * i, bg0 + koff + i * bstep);
            CP_COMMIT();
        }

        const uint32_t st = (uint32_t)cur * ST2;
#pragma unroll
        for (int s = 0; s < 4; ++s) {
            uint32_t af[2][4], bf[2][4];
#pragma unroll
            for (int i = 0; i < 2; ++i) {
                uint32_t addr = sb + st + a_rb[i] +
                                ((uint32_t)((2 * s + a_hi) ^ a_r7[i]) << 4);
                LDSM_X4(af[i], addr);
            }
#pragma unroll
            for (int g = 0; g < 2; ++g) {
                uint32_t addr = sb + st + 8192u + b_rb[g] +
                                ((uint32_t)((2 * s + b_hi) ^ b_r7[g]) << 4);
                LDSM_X4(bf[g], addr);
            }
#pragma unroll
            for (int i = 0; i < 2; ++i)
#pragma unroll
                for (int n = 0; n < 4; ++n)
                    MMA_BF16(acc[i][n], af[i], bf[n >> 1][(n & 1) * 2], bf[n >> 1][(n & 1) * 2 + 1]);
        }
        cur = (cur == 2) ? 0 : cur + 1;
        nxt = (nxt == 2) ? 0 : nxt + 1;
    }

    const int gid = lane >> 2, tig = lane & 3;
#pragma unroll
    for (int i = 0; i < 2; ++i) {
        int r_lo = row0 + wm * 32 + i * 16 + gid;
        int r_hi = r_lo + 8;
#pragma unroll
        for (int n = 0; n < 4; ++n) {
            int c = col0 + wn * 32 + n * 8 + tig * 2;
            if (c < Ncols) {
                float b0 = bias[c], b1 = bias[c + 1];
                float v0 = lrelu(acc[i][n][0] + b0), v1 = lrelu(acc[i][n][1] + b1);
                float v2 = lrelu(acc[i][n][2] + b0), v3 = lrelu(acc[i][n][3] + b1);
                *(float2*)(C + (size_t)r_lo * Ncols + c) = make_float2(v0, v1);
                *(float2*)(C + (size_t)r_hi * Ncols + c) = make_float2(v2, v3);
            }
        }
    }
}

// ---------------- launcher: R16 chain (fork/join transposes + PDL GEMMs) ----------------
static cudaStream_t g_s1 = nullptr;
static cudaEvent_t  g_evF = nullptr, g_evT = nullptr;

extern "C" void kernel_launch(void* const* d_in, const int* in_sizes, int n_in,
                              void* d_out, int out_size) {
    const float* x   = (const float*)d_in[0];
    const float* c1w = (const float*)d_in[1];   // conv1_w [4,2048]
    const float* p1W = (const float*)d_in[4];   // prop1_W [2048,1100]
    const float* p1B = (const float*)d_in[5];   // prop1_B [1100]
    const float* c2w = (const float*)d_in[6];   // conv2_w [4,1100]
    const float* p2W = (const float*)d_in[9];   // prop2_W [1100,512]
    const float* p2B = (const float*)d_in[10];  // prop2_B [512]
    float* out = (float*)d_out;                 // [2048,512]
    // d_in[2,3,7,8]: pool weights — dead code (adjacency normalizes to identity)

    __nv_bfloat16 *g1, *g2, *bt1, *bt2;
    cudaGetSymbolAddress((void**)&g1,  g_g1);
    cudaGetSymbolAddress((void**)&g2,  g_g2);
    cudaGetSymbolAddress((void**)&bt1, g_bt1);
    cudaGetSymbolAddress((void**)&bt2, g_bt2);

    if (!g_s1) {    // first call is the uncaptured correctness run: safe to create here
        cudaStreamCreateWithFlags(&g_s1, cudaStreamNonBlocking);
        cudaEventCreateWithFlags(&g_evF, cudaEventDisableTiming);
        cudaEventCreateWithFlags(&g_evT, cudaEventDisableTiming);
        cudaFuncSetAttribute(gemm1_fused, cudaFuncAttributeMaxDynamicSharedMemorySize, SMEM1);
        cudaFuncSetAttribute(gemm2_small, cudaFuncAttributeMaxDynamicSharedMemorySize, SMEM2);
    }

    // fork FROM the capture stream: side stream joins the capture via evF
    cudaEventRecord(g_evF, 0);
    cudaStreamWaitEvent(g_s1, g_evF, 0);

    // side stream (in-graph): weight transposes, parallel with conv1
    transpose_bf16<<<dim3(Fdim / 32, N1PAD / 32), dim3(32, 8), 0, g_s1>>>(
        p1W, bt1, Fdim, HID, Fdim, N1PAD);
    transpose_bf16<<<dim3(K2PAD / 32, NCLS / 32), dim3(32, 8), 0, g_s1>>>(
        p2W, bt2, HID, NCLS, K2PAD, NCLS);
    cudaEventRecord(g_evT, g_s1);

    // capture stream: conv1 (16 cols/thread)
    {
        long total = (long)M1 * (Fdim / 16);
        node_conv4_bf16<Fdim><<<(int)((total + 255) / 256), 256>>>(x, c1w, g1, M1);
    }
    cudaStreamWaitEvent(0, g_evT, 0);

    // GEMM1 with PDL: launches during conv tail, griddepsync gates data reads
    {
        cudaLaunchAttribute attr[1];
        attr[0].id = cudaLaunchAttributeProgrammaticStreamSerialization;
        attr[0].val.programmaticStreamSerializationAllowed = 1;
        cudaLaunchConfig_t cfg{};
        cfg.gridDim = dim3(N1PAD / 128, M1 / 128);
        cfg.blockDim = dim3(256);
        cfg.dynamicSmemBytes = SMEM1;
        cfg.stream = 0;
        cfg.attrs = attr;
        cfg.numAttrs = 1;
        cudaLaunchKernelEx(&cfg, gemm1_fused,
                           (const __nv_bfloat16*)g1, (const __nv_bfloat16*)bt1, p1B, c2w,
                           (__nv_bfloat16*)g2, HID, Fdim, Fdim, Fdim / 64, K2PAD);
    }

    // GEMM2 with PDL: launches during GEMM1 tail
    {
        cudaLaunchAttribute attr[1];
        attr[0].id = cudaLaunchAttributeProgrammaticStreamSerialization;
        attr[0].val.programmaticStreamSerializationAllowed = 1;
        cudaLaunchConfig_t cfg{};
        cfg.gridDim = dim3(NCLS / 64, M2 / 64);
        cfg.blockDim = dim3(128);
        cfg.dynamicSmemBytes = SMEM2;
        cfg.stream = 0;
        cfg.attrs = attr;
        cfg.numAttrs = 1;
        cudaLaunchKernelEx(&cfg, gemm2_small,
                           (const __nv_bfloat16*)g2, (const __nv_bfloat16*)bt2, p2B, out,
                           NCLS, K2PAD, K2PAD, K2PAD / 64);
    }
}